// round 2
// baseline (speedup 1.0000x reference)
#include <cuda_runtime.h>
#include <math.h>

// ---------------- problem constants ----------------
#define TT   256
#define BB   32
#define HH   512
#define GG   2048      // 4*H
#define EE   256
#define H2   1024      // 2*H
#define LL   9
#define MM   (TT*BB)   // 8192

// ---------------- device scratch (static, no runtime alloc) ----------------
__device__ float g_x0[MM * EE];          // embedded input, time-major (t,b,e)
__device__ float g_x1[MM * H2];          // layer0 output (t,b,2H)
__device__ float g_x2[MM * H2];          // layer1 output
__device__ float g_pre_f[(size_t)MM * GG];
__device__ float g_pre_r[(size_t)MM * GG];
__device__ float g_wT[4 * HH * GG];      // transposed w_hh: [mat][k][r]
__device__ float g_h[2][2][BB][HH];      // double-buffered hidden state [buf][dir][b][k]
__device__ unsigned g_cnt;
__device__ volatile unsigned g_gen;

// ---------------- software grid barrier ----------------
__device__ __forceinline__ void grid_barrier(unsigned nb) {
    __threadfence();
    __syncthreads();
    if (threadIdx.x == 0) {
        unsigned gen = g_gen;
        __threadfence();
        if (atomicAdd(&g_cnt, 1u) == nb - 1u) {
            atomicExch(&g_cnt, 0u);
            __threadfence();
            g_gen = gen + 1u;
        } else {
            while (g_gen == gen) { __nanosleep(64); }
        }
        __threadfence();
    }
    __syncthreads();
}

__device__ __forceinline__ float sigf(float x) { return 1.0f / (1.0f + expf(-x)); }

// ---------------- embedding: x0[t][b][:] = emb[ids[b][t]] ----------------
__global__ void embed_k(const int* __restrict__ ids, const float* __restrict__ table,
                        float* __restrict__ x0) {
    int gid = blockIdx.x * blockDim.x + threadIdx.x;   // one float4 each
    if (gid >= MM * EE / 4) return;
    int e4 = gid & 63;          // 64 float4 per row (E=256)
    int m  = gid >> 6;          // m = t*32 + b
    int t  = m >> 5;
    int b  = m & 31;
    int id = ids[b * TT + t];
    reinterpret_cast<float4*>(x0)[gid] =
        reinterpret_cast<const float4*>(table)[(size_t)id * 64 + e4];
}

// ---------------- transpose w_hh (2048x512 -> 512x2048), 4 matrices ----------------
__global__ void transpose_whh(const float* __restrict__ a, const float* __restrict__ b,
                              const float* __restrict__ c, const float* __restrict__ d,
                              float* __restrict__ wT) {
    int idx = blockIdx.x * blockDim.x + threadIdx.x;
    if (idx >= 4 * GG * HH) return;
    int mat = idx >> 20;
    int rem = idx & 0xFFFFF;
    int r = rem >> 9, k = rem & 511;
    const float* src = (mat == 0) ? a : (mat == 1) ? b : (mat == 2) ? c : d;
    wT[(size_t)mat * (HH * GG) + (size_t)k * GG + r] = src[rem];
}

// ---------------- SGEMM: C[m][r] = sum_k A[m][k]*W[r][k] + b1[r] + b2[r] --------
// A: M x K row-major. W: 2048 x K row-major. Tile 128x128x8, 8x8 microtile.
__global__ __launch_bounds__(256) void gemm_nt_128(
    const float* __restrict__ A, int K,
    const float* __restrict__ Wf, const float* __restrict__ Wr,
    const float* __restrict__ b1f, const float* __restrict__ b2f,
    const float* __restrict__ b1r, const float* __restrict__ b2r,
    float* __restrict__ Cf, float* __restrict__ Cr) {
    const int N = GG;
    const float* W;  const float* b1; const float* b2; float* C;
    if (blockIdx.z == 0) { W = Wf; b1 = b1f; b2 = b2f; C = Cf; }
    else                 { W = Wr; b1 = b1r; b2 = b2r; C = Cr; }

    __shared__ float As[8][132];
    __shared__ float Bs[8][132];
    int tid = threadIdx.x;
    int m0 = blockIdx.y * 128, n0 = blockIdx.x * 128;
    int lr = tid >> 1;
    int lc = (tid & 1) * 4;
    int tx = tid & 15, ty = tid >> 4;

    float acc[8][8];
#pragma unroll
    for (int i = 0; i < 8; i++)
#pragma unroll
        for (int j = 0; j < 8; j++) acc[i][j] = 0.0f;

    for (int k0 = 0; k0 < K; k0 += 8) {
        float4 av = *reinterpret_cast<const float4*>(&A[(size_t)(m0 + lr) * K + k0 + lc]);
        float4 bv = *reinterpret_cast<const float4*>(&W[(size_t)(n0 + lr) * K + k0 + lc]);
        As[lc + 0][lr] = av.x; As[lc + 1][lr] = av.y;
        As[lc + 2][lr] = av.z; As[lc + 3][lr] = av.w;
        Bs[lc + 0][lr] = bv.x; Bs[lc + 1][lr] = bv.y;
        Bs[lc + 2][lr] = bv.z; Bs[lc + 3][lr] = bv.w;
        __syncthreads();
#pragma unroll
        for (int kk = 0; kk < 8; kk++) {
            float4 a0 = *reinterpret_cast<const float4*>(&As[kk][ty * 8]);
            float4 a1 = *reinterpret_cast<const float4*>(&As[kk][ty * 8 + 4]);
            float4 c0 = *reinterpret_cast<const float4*>(&Bs[kk][tx * 8]);
            float4 c1 = *reinterpret_cast<const float4*>(&Bs[kk][tx * 8 + 4]);
            float a[8] = {a0.x, a0.y, a0.z, a0.w, a1.x, a1.y, a1.z, a1.w};
            float b[8] = {c0.x, c0.y, c0.z, c0.w, c1.x, c1.y, c1.z, c1.w};
#pragma unroll
            for (int i = 0; i < 8; i++)
#pragma unroll
                for (int j = 0; j < 8; j++) acc[i][j] = fmaf(a[i], b[j], acc[i][j]);
        }
        __syncthreads();
    }
#pragma unroll
    for (int i = 0; i < 8; i++) {
        int m = m0 + ty * 8 + i;
#pragma unroll
        for (int j = 0; j < 8; j += 4) {
            int n = n0 + tx * 8 + j;
            float4 o;
            o.x = acc[i][j + 0] + b1[n + 0] + b2[n + 0];
            o.y = acc[i][j + 1] + b1[n + 1] + b2[n + 1];
            o.z = acc[i][j + 2] + b1[n + 2] + b2[n + 2];
            o.w = acc[i][j + 3] + b1[n + 3] + b2[n + 3];
            *reinterpret_cast<float4*>(&C[(size_t)m * N + n]) = o;
        }
    }
}

// ---------------- persistent bidirectional LSTM recurrence ----------------
// 128 blocks: 0..63 forward (j0 = blk*8), 64..127 reverse. 256 threads.
// Each block: 8 hidden units * 4 gates * 32 batch = 1024 dots of length 512/step.
__global__ __launch_bounds__(256) void lstm_rec(
    const float* __restrict__ pre_f, const float* __restrict__ pre_r,
    const float* __restrict__ wT_f, const float* __restrict__ wT_r,
    float* __restrict__ xout) {
    extern __shared__ float sm[];
    float* sh_h = sm;              // 32*512
    float* sh_g = sm + BB * HH;    // 32*32 gates [b][g*8+jj]

    int blk = blockIdx.x;
    int dir = (blk >= 64) ? 1 : 0;
    int jb = dir ? blk - 64 : blk;
    int j0 = jb * 8;
    const float* pre = dir ? pre_r : pre_f;
    const float* wT  = dir ? wT_r  : wT_f;

    int tid = threadIdx.x;
    int lane = tid & 31, warp = tid >> 5;
    int gsel = lane >> 3, jj = lane & 7;
    int r = gsel * HH + j0 + jj;
    int b_u = tid >> 3, j_u = tid & 7;

    g_h[0][dir][b_u][j0 + j_u] = 0.0f;
    float c = 0.0f;
    const float* wp = wT + r;

    grid_barrier(128);
    for (int s = 0; s < TT; s++) {
        int t = dir ? (TT - 1 - s) : s;
        // broadcast h_prev into smem
        const float4* hs = reinterpret_cast<const float4*>(&g_h[s & 1][dir][0][0]);
        float4* hd = reinterpret_cast<float4*>(sh_h);
#pragma unroll
        for (int i = 0; i < 16; i++) hd[tid + 256 * i] = hs[tid + 256 * i];
        __syncthreads();

        const float* prept = pre + (size_t)t * (BB * GG);
        float acc0 = prept[(warp) * GG + r];
        float acc1 = prept[(warp + 8) * GG + r];
        float acc2 = prept[(warp + 16) * GG + r];
        float acc3 = prept[(warp + 24) * GG + r];
        const float* h0p = sh_h + warp * HH;
#pragma unroll 4
        for (int k = 0; k < HH; k += 4) {
            float w0 = wp[(size_t)(k + 0) * GG];
            float w1 = wp[(size_t)(k + 1) * GG];
            float w2 = wp[(size_t)(k + 2) * GG];
            float w3 = wp[(size_t)(k + 3) * GG];
            float4 h0 = *reinterpret_cast<const float4*>(h0p + k);
            float4 h1 = *reinterpret_cast<const float4*>(h0p + 8 * HH + k);
            float4 h2 = *reinterpret_cast<const float4*>(h0p + 16 * HH + k);
            float4 h3 = *reinterpret_cast<const float4*>(h0p + 24 * HH + k);
            acc0 = fmaf(h0.x, w0, fmaf(h0.y, w1, fmaf(h0.z, w2, fmaf(h0.w, w3, acc0))));
            acc1 = fmaf(h1.x, w0, fmaf(h1.y, w1, fmaf(h1.z, w2, fmaf(h1.w, w3, acc1))));
            acc2 = fmaf(h2.x, w0, fmaf(h2.y, w1, fmaf(h2.z, w2, fmaf(h2.w, w3, acc2))));
            acc3 = fmaf(h3.x, w0, fmaf(h3.y, w1, fmaf(h3.z, w2, fmaf(h3.w, w3, acc3))));
        }
        sh_g[(warp) * 32 + lane] = acc0;
        sh_g[(warp + 8) * 32 + lane] = acc1;
        sh_g[(warp + 16) * 32 + lane] = acc2;
        sh_g[(warp + 24) * 32 + lane] = acc3;
        __syncthreads();

        float gi = sh_g[b_u * 32 + j_u];
        float gf = sh_g[b_u * 32 + 8 + j_u];
        float gg = sh_g[b_u * 32 + 16 + j_u];
        float go = sh_g[b_u * 32 + 24 + j_u];
        c = sigf(gf) * c + sigf(gi) * tanhf(gg);
        float h = sigf(go) * tanhf(c);
        g_h[(s + 1) & 1][dir][b_u][j0 + j_u] = h;
        xout[((size_t)t * BB + b_u) * H2 + dir * HH + j0 + j_u] = h;
        grid_barrier(128);
    }
}

// ---------------- classifier: emissions[b][t][l] = x2[t][b][:] . cls_w[l][:] + b -----
__global__ void cls_k(const float* __restrict__ x2, const float* __restrict__ w,
                      const float* __restrict__ bias, float* __restrict__ out) {
    int gw = (blockIdx.x * blockDim.x + threadIdx.x) >> 5;
    int lane = threadIdx.x & 31;
    if (gw >= MM) return;
    const float* xr = x2 + (size_t)gw * H2;
    float acc[LL];
#pragma unroll
    for (int l = 0; l < LL; l++) acc[l] = 0.0f;
    for (int k = lane; k < H2; k += 32) {
        float xv = xr[k];
#pragma unroll
        for (int l = 0; l < LL; l++) acc[l] = fmaf(xv, w[l * H2 + k], acc[l]);
    }
#pragma unroll
    for (int l = 0; l < LL; l++) {
#pragma unroll
        for (int off = 16; off > 0; off >>= 1)
            acc[l] += __shfl_xor_sync(0xffffffffu, acc[l], off);
    }
    if (lane == 0) {
        int t = gw >> 5, b = gw & 31;
        float* o = out + 1 + ((size_t)b * TT + t) * LL;
#pragma unroll
        for (int l = 0; l < LL; l++) o[l] = acc[l] + bias[l];
    }
}

// ---------------- CRF negative log-likelihood (single block) ----------------
__global__ void crf_k(const float* __restrict__ dout, const int* __restrict__ labels,
                      const int* __restrict__ mask, const float* __restrict__ start,
                      const float* __restrict__ endv, const float* __restrict__ trans,
                      float* __restrict__ out) {
    __shared__ float alpha[BB][LL];
    __shared__ float sc[BB];
    __shared__ float lz[BB];
    __shared__ int   prev[BB];
    __shared__ float tr[LL][LL];
    int tid = threadIdx.x;
    int b = tid / LL, l = tid % LL;
    if (tid < LL * LL) tr[tid / LL][tid % LL] = trans[tid];
    __syncthreads();
    const float* em = dout + 1;

    alpha[b][l] = start[l] + em[((size_t)b * TT) * LL + l];
    if (l == 0) {
        int tg = labels[b * TT]; if (tg < 0) tg = 0;
        sc[b] = start[tg] + em[((size_t)b * TT) * LL + tg];
        prev[b] = tg;
    }
    __syncthreads();

    for (int t = 1; t < TT; t++) {
        int on = mask[b * TT + t];
        float m = -1e30f;
#pragma unroll
        for (int p = 0; p < LL; p++) m = fmaxf(m, alpha[b][p] + tr[p][l]);
        float s = 0.0f;
#pragma unroll
        for (int p = 0; p < LL; p++) s += expf(alpha[b][p] + tr[p][l] - m);
        float nxt = m + logf(s) + em[((size_t)b * TT + t) * LL + l];
        __syncthreads();
        if (on) alpha[b][l] = nxt;
        if (l == 0) {
            int tg = labels[b * TT + t]; if (tg < 0) tg = 0;
            float mk = (float)mask[b * TT + t];
            sc[b] += (tr[prev[b]][tg] + em[((size_t)b * TT + t) * LL + tg]) * mk;
            if (on) prev[b] = tg;
        }
        __syncthreads();
    }
    if (l == 0) {
        sc[b] += endv[prev[b]];
        float m = -1e30f;
#pragma unroll
        for (int p = 0; p < LL; p++) m = fmaxf(m, alpha[b][p] + endv[p]);
        float s = 0.0f;
#pragma unroll
        for (int p = 0; p < LL; p++) s += expf(alpha[b][p] + endv[p] - m);
        lz[b] = m + logf(s);
    }
    __syncthreads();
    if (tid == 0) {
        float loss = 0.0f;
        for (int bb = 0; bb < BB; bb++) loss += sc[bb] - lz[bb];
        out[0] = -loss / (float)BB;
    }
}

// ---------------- host launch ----------------
extern "C" void kernel_launch(void* const* d_in, const int* in_sizes, int n_in,
                              void* d_out, int out_size) {
    const int*   ids    = (const int*)d_in[0];
    const int*   amask  = (const int*)d_in[1];
    const int*   labels = (const int*)d_in[2];
    const float* emb    = (const float*)d_in[3];
    const float* w_ih_l0_f = (const float*)d_in[4];
    const float* w_hh_l0_f = (const float*)d_in[5];
    const float* b_ih_l0_f = (const float*)d_in[6];
    const float* b_hh_l0_f = (const float*)d_in[7];
    const float* w_ih_l0_r = (const float*)d_in[8];
    const float* w_hh_l0_r = (const float*)d_in[9];
    const float* b_ih_l0_r = (const float*)d_in[10];
    const float* b_hh_l0_r = (const float*)d_in[11];
    const float* w_ih_l1_f = (const float*)d_in[12];
    const float* w_hh_l1_f = (const float*)d_in[13];
    const float* b_ih_l1_f = (const float*)d_in[14];
    const float* b_hh_l1_f = (const float*)d_in[15];
    const float* w_ih_l1_r = (const float*)d_in[16];
    const float* w_hh_l1_r = (const float*)d_in[17];
    const float* b_ih_l1_r = (const float*)d_in[18];
    const float* b_hh_l1_r = (const float*)d_in[19];
    const float* cls_w  = (const float*)d_in[20];
    const float* cls_b  = (const float*)d_in[21];
    const float* crf_s  = (const float*)d_in[22];
    const float* crf_e  = (const float*)d_in[23];
    const float* crf_t  = (const float*)d_in[24];
    float* out = (float*)d_out;

    float *x0, *x1, *x2, *pref, *prer, *wT;
    cudaGetSymbolAddress((void**)&x0,   g_x0);
    cudaGetSymbolAddress((void**)&x1,   g_x1);
    cudaGetSymbolAddress((void**)&x2,   g_x2);
    cudaGetSymbolAddress((void**)&pref, g_pre_f);
    cudaGetSymbolAddress((void**)&prer, g_pre_r);
    cudaGetSymbolAddress((void**)&wT,   g_wT);

    const int rec_smem = (BB * HH + BB * 32) * (int)sizeof(float);  // 69632
    cudaFuncSetAttribute(lstm_rec, cudaFuncAttributeMaxDynamicSharedMemorySize, rec_smem);

    embed_k<<<(MM * EE / 4 + 255) / 256, 256>>>(ids, emb, x0);
    transpose_whh<<<(4 * GG * HH + 255) / 256, 256>>>(w_hh_l0_f, w_hh_l0_r,
                                                      w_hh_l1_f, w_hh_l1_r, wT);
    dim3 gg(GG / 128, MM / 128, 2);
    gemm_nt_128<<<gg, 256>>>(x0, EE, w_ih_l0_f, w_ih_l0_r,
                             b_ih_l0_f, b_hh_l0_f, b_ih_l0_r, b_hh_l0_r, pref, prer);
    lstm_rec<<<128, 256, rec_smem>>>(pref, prer, wT, wT + HH * GG, x1);
    gemm_nt_128<<<gg, 256>>>(x1, H2, w_ih_l1_f, w_ih_l1_r,
                             b_ih_l1_f, b_hh_l1_f, b_ih_l1_r, b_hh_l1_r, pref, prer);
    lstm_rec<<<128, 256, rec_smem>>>(pref, prer, wT + 2 * HH * GG, wT + 3 * HH * GG, x2);
    cls_k<<<(MM * 32 + 255) / 256, 256>>>(x2, cls_w, cls_b, out);
    crf_k<<<1, BB * LL>>>(out, labels, amask, crf_s, crf_e, crf_t, out);
}

// round 5
// speedup vs baseline: 2.1001x; 2.1001x over previous
#include <cuda_runtime.h>
#include <math.h>

// ---------------- problem constants ----------------
#define TT   256
#define BB   32
#define HH   512
#define GG   2048      // 4*H
#define EE   256
#define H2   1024      // 2*H
#define LL   9
#define MM   (TT*BB)   // 8192

// ---------------- device scratch ----------------
__device__ float g_x0[MM * EE];
__device__ float g_x1[MM * H2];
__device__ float g_x2[MM * H2];
__device__ float g_pre_f[(size_t)MM * GG];
__device__ float g_pre_r[(size_t)MM * GG];
__device__ float g_wT[4 * HH * GG];          // [mat][k][r]
__device__ float g_hT[2][2][HH][BB];         // [buf][dir][k][b] transposed hidden
__device__ unsigned g_cnt;
__device__ volatile unsigned g_gen;

// ---------------- packed f32x2 helpers ----------------
typedef unsigned long long ull;
union F4U { float4 f; ull u[2]; };

__device__ __forceinline__ ull pk2(float lo, float hi) {
    ull r; asm("mov.b64 %0, {%1,%2};" : "=l"(r) : "f"(lo), "f"(hi)); return r;
}
__device__ __forceinline__ ull fma2(ull a, ull b, ull c) {
    ull d; asm("fma.rn.f32x2 %0, %1, %2, %3;" : "=l"(d) : "l"(a), "l"(b), "l"(c)); return d;
}
__device__ __forceinline__ void upk2(ull v, float& lo, float& hi) {
    asm("mov.b64 {%0,%1}, %2;" : "=f"(lo), "=f"(hi) : "l"(v));
}

// ---------------- software grid barrier ----------------
__device__ __forceinline__ void grid_barrier(unsigned nb) {
    __threadfence();
    __syncthreads();
    if (threadIdx.x == 0) {
        unsigned gen = g_gen;
        __threadfence();
        if (atomicAdd(&g_cnt, 1u) == nb - 1u) {
            atomicExch(&g_cnt, 0u);
            __threadfence();
            g_gen = gen + 1u;
        } else {
            while (g_gen == gen) { }
        }
        __threadfence();
    }
    __syncthreads();
}

__device__ __forceinline__ float sigf(float x) { return 1.0f / (1.0f + __expf(-x)); }
__device__ __forceinline__ float tanhfast(float x) {
    float e = __expf(2.0f * x);
    return (e - 1.0f) / (e + 1.0f);
}

// ---------------- embedding ----------------
__global__ void embed_k(const int* __restrict__ ids, const float* __restrict__ table,
                        float* __restrict__ x0) {
    int gid = blockIdx.x * blockDim.x + threadIdx.x;
    if (gid >= MM * EE / 4) return;
    int e4 = gid & 63;
    int m  = gid >> 6;
    int t  = m >> 5;
    int b  = m & 31;
    int id = ids[b * TT + t];
    reinterpret_cast<float4*>(x0)[gid] =
        reinterpret_cast<const float4*>(table)[(size_t)id * 64 + e4];
}

// ---------------- transpose w_hh ----------------
__global__ void transpose_whh(const float* __restrict__ a, const float* __restrict__ b,
                              const float* __restrict__ c, const float* __restrict__ d,
                              float* __restrict__ wT) {
    int idx = blockIdx.x * blockDim.x + threadIdx.x;
    if (idx >= 4 * GG * HH) return;
    int mat = idx >> 20;
    int rem = idx & 0xFFFFF;
    int r = rem >> 9, k = rem & 511;
    const float* src = (mat == 0) ? a : (mat == 1) ? b : (mat == 2) ? c : d;
    wT[(size_t)mat * (HH * GG) + (size_t)k * GG + r] = src[rem];
}

// ---------------- SGEMM (f32x2, double-buffered regs) ----------------
__global__ __launch_bounds__(256) void gemm_nt_128(
    const float* __restrict__ A, int K,
    const float* __restrict__ Wf, const float* __restrict__ Wr,
    const float* __restrict__ b1f, const float* __restrict__ b2f,
    const float* __restrict__ b1r, const float* __restrict__ b2r,
    float* __restrict__ Cf, float* __restrict__ Cr) {
    const int N = GG;
    const float* W;  const float* b1; const float* b2; float* C;
    if (blockIdx.z == 0) { W = Wf; b1 = b1f; b2 = b2f; C = Cf; }
    else                 { W = Wr; b1 = b1r; b2 = b2r; C = Cr; }

    __shared__ float As[8][132];
    __shared__ float Bs[8][132];
    int tid = threadIdx.x;
    int m0 = blockIdx.y * 128, n0 = blockIdx.x * 128;
    int lr = tid >> 1;
    int lc = (tid & 1) * 4;
    int tx = tid & 15, ty = tid >> 4;

    ull acc[8][4];
#pragma unroll
    for (int i = 0; i < 8; i++)
#pragma unroll
        for (int j = 0; j < 4; j++) acc[i][j] = 0ull;

    const float* Ap = &A[(size_t)(m0 + lr) * K + lc];
    const float* Wp = &W[(size_t)(n0 + lr) * K + lc];

    float4 av = *reinterpret_cast<const float4*>(Ap);
    float4 bv = *reinterpret_cast<const float4*>(Wp);

    for (int k0 = 0; k0 < K; k0 += 8) {
        As[lc + 0][lr] = av.x; As[lc + 1][lr] = av.y;
        As[lc + 2][lr] = av.z; As[lc + 3][lr] = av.w;
        Bs[lc + 0][lr] = bv.x; Bs[lc + 1][lr] = bv.y;
        Bs[lc + 2][lr] = bv.z; Bs[lc + 3][lr] = bv.w;
        __syncthreads();
        if (k0 + 8 < K) {
            av = *reinterpret_cast<const float4*>(Ap + k0 + 8);
            bv = *reinterpret_cast<const float4*>(Wp + k0 + 8);
        }
#pragma unroll
        for (int kk = 0; kk < 8; kk++) {
            F4U a0, a1, c0, c1;
            a0.f = *reinterpret_cast<const float4*>(&As[kk][ty * 8]);
            a1.f = *reinterpret_cast<const float4*>(&As[kk][ty * 8 + 4]);
            c0.f = *reinterpret_cast<const float4*>(&Bs[kk][tx * 8]);
            c1.f = *reinterpret_cast<const float4*>(&Bs[kk][tx * 8 + 4]);
            ull bp0 = c0.u[0], bp1 = c0.u[1], bp2 = c1.u[0], bp3 = c1.u[1];
            float as[8] = {a0.f.x, a0.f.y, a0.f.z, a0.f.w,
                           a1.f.x, a1.f.y, a1.f.z, a1.f.w};
#pragma unroll
            for (int i = 0; i < 8; i++) {
                ull ap = pk2(as[i], as[i]);
                acc[i][0] = fma2(ap, bp0, acc[i][0]);
                acc[i][1] = fma2(ap, bp1, acc[i][1]);
                acc[i][2] = fma2(ap, bp2, acc[i][2]);
                acc[i][3] = fma2(ap, bp3, acc[i][3]);
            }
        }
        __syncthreads();
    }
#pragma unroll
    for (int i = 0; i < 8; i++) {
        int m = m0 + ty * 8 + i;
        float r[8];
#pragma unroll
        for (int j = 0; j < 4; j++) upk2(acc[i][j], r[2 * j], r[2 * j + 1]);
#pragma unroll
        for (int j = 0; j < 8; j += 4) {
            int n = n0 + tx * 8 + j;
            float4 o;
            o.x = r[j + 0] + b1[n + 0] + b2[n + 0];
            o.y = r[j + 1] + b1[n + 1] + b2[n + 1];
            o.z = r[j + 2] + b1[n + 2] + b2[n + 2];
            o.w = r[j + 3] + b1[n + 3] + b2[n + 3];
            *reinterpret_cast<float4*>(&C[(size_t)m * N + n]) = o;
        }
    }
}

// ---------------- persistent bidirectional LSTM recurrence (v2) ----------------
// 128 blocks (64/dir), 256 threads. Block covers 8 units j0..j0+8 (32 gate rows)
// for all 32 batches. W tile resident in smem; h read transposed from L2.
// dot: warp = k-chunk (64 k each), 32 lanes tile 32r x 32b as 4r x 8b.
__global__ __launch_bounds__(256) void lstm_rec(
    const float* __restrict__ pre_f, const float* __restrict__ pre_r,
    const float* __restrict__ wT_f, const float* __restrict__ wT_r,
    float* __restrict__ xout) {
    extern __shared__ float sm[];
    float* sW = sm;                       // [512][32]        16384 floats
    float* sP = sm + 512 * 32;            // [8][32][34]      8704 floats
    float* sG = sP + 8 * 32 * 34;         // [32][33]         1056 floats

    int blk = blockIdx.x;
    int dir = blk >> 6;
    int j0 = (blk & 63) * 8;
    const float* pre = dir ? pre_r : pre_f;
    const float* wT  = dir ? wT_r  : wT_f;

    int tid = threadIdx.x;
    int warp = tid >> 5, lane = tid & 31;
    int it = lane >> 2, jt = lane & 3;       // dot tile: 4r x 8b
    int ua = warp, ba = lane;                // activation: (unit, batch)
    int rr = tid >> 3, bq = tid & 7;         // reduction: row rr, batches bq*4..+4
    int b0 = bq * 4;
    int r_glob = (rr >> 3) * HH + j0 + (rr & 7);

    // load W tile once: sW[k][g*8+u] = wT[k][g*512+j0+u]
    for (int i = tid; i < 512 * 32; i += 256) {
        int k = i >> 5, rl = i & 31;
        int g = rl >> 3, u = rl & 7;
        sW[k * 32 + rl] = wT[(size_t)k * GG + g * HH + j0 + u];
    }

    // zero h buffer 0 (this block's 8 k-rows)
    g_hT[0][dir][j0 + ua][ba] = 0.0f;
    float creg = 0.0f;

    grid_barrier(128);

    for (int s = 0; s < TT; s++) {
        int t = dir ? (TT - 1 - s) : s;
        int cur = s & 1, nxt = cur ^ 1;
        const float* hT = &g_hT[cur][dir][0][0];

        // prefetch pre for reduction phase (hidden behind dot loop)
        const float* pre_t = pre + (size_t)t * (BB * GG) + r_glob;
        float p0 = pre_t[(size_t)(b0 + 0) * GG];
        float p1 = pre_t[(size_t)(b0 + 1) * GG];
        float p2 = pre_t[(size_t)(b0 + 2) * GG];
        float p3 = pre_t[(size_t)(b0 + 3) * GG];

        // dot: this warp's k-chunk
        ull acc[4][4];
#pragma unroll
        for (int i = 0; i < 4; i++)
#pragma unroll
            for (int p = 0; p < 4; p++) acc[i][p] = 0ull;

        int kbase = warp * 64;
        const float* hrow = hT + (size_t)kbase * BB + jt * 8;
        const float* wrow = sW + kbase * 32 + it * 4;
#pragma unroll 4
        for (int kk = 0; kk < 64; kk++) {
            F4U w4, ha, hb;
            w4.f = *reinterpret_cast<const float4*>(wrow + kk * 32);
            ha.f = *reinterpret_cast<const float4*>(hrow + kk * BB);
            hb.f = *reinterpret_cast<const float4*>(hrow + kk * BB + 4);
            ull h0 = ha.u[0], h1 = ha.u[1], h2 = hb.u[0], h3 = hb.u[1];
            ull w;
            w = pk2(w4.f.x, w4.f.x);
            acc[0][0] = fma2(w, h0, acc[0][0]); acc[0][1] = fma2(w, h1, acc[0][1]);
            acc[0][2] = fma2(w, h2, acc[0][2]); acc[0][3] = fma2(w, h3, acc[0][3]);
            w = pk2(w4.f.y, w4.f.y);
            acc[1][0] = fma2(w, h0, acc[1][0]); acc[1][1] = fma2(w, h1, acc[1][1]);
            acc[1][2] = fma2(w, h2, acc[1][2]); acc[1][3] = fma2(w, h3, acc[1][3]);
            w = pk2(w4.f.z, w4.f.z);
            acc[2][0] = fma2(w, h0, acc[2][0]); acc[2][1] = fma2(w, h1, acc[2][1]);
            acc[2][2] = fma2(w, h2, acc[2][2]); acc[2][3] = fma2(w, h3, acc[2][3]);
            w = pk2(w4.f.w, w4.f.w);
            acc[3][0] = fma2(w, h0, acc[3][0]); acc[3][1] = fma2(w, h1, acc[3][1]);
            acc[3][2] = fma2(w, h2, acc[3][2]); acc[3][3] = fma2(w, h3, acc[3][3]);
        }

        // write partials sP[warp][it*4+i][jt*8+2p..]
#pragma unroll
        for (int i = 0; i < 4; i++) {
            float* row = sP + ((warp * 32) + it * 4 + i) * 34 + jt * 8;
#pragma unroll
            for (int p = 0; p < 4; p++) {
                float lo, hi; upk2(acc[i][p], lo, hi);
                row[2 * p] = lo; row[2 * p + 1] = hi;
            }
        }
        __syncthreads();

        // reduce 8 chunks + pre -> gates sG[rr][b0..b0+4]
        {
            float s0 = p0, s1 = p1, s2 = p2, s3 = p3;
#pragma unroll
            for (int c = 0; c < 8; c++) {
                const float* row = sP + ((c * 32) + rr) * 34 + b0;
                float2 x = *reinterpret_cast<const float2*>(row);
                float2 y = *reinterpret_cast<const float2*>(row + 2);
                s0 += x.x; s1 += x.y; s2 += y.x; s3 += y.y;
            }
            float* g = sG + rr * 33 + b0;
            g[0] = s0; g[1] = s1; g[2] = s2; g[3] = s3;
        }
        __syncthreads();

        // activation (thread <-> (unit ua, batch ba) fixed across steps)
        {
            float gi = sG[(0 + ua) * 33 + ba];
            float gf = sG[(8 + ua) * 33 + ba];
            float gc = sG[(16 + ua) * 33 + ba];
            float go = sG[(24 + ua) * 33 + ba];
            creg = sigf(gf) * creg + sigf(gi) * tanhfast(gc);
            float h = sigf(go) * tanhfast(creg);
            g_hT[nxt][dir][j0 + ua][ba] = h;
            xout[((size_t)t * BB + ba) * H2 + dir * HH + j0 + ua] = h;
        }
        grid_barrier(128);
    }
}

// ---------------- classifier ----------------
__global__ void cls_k(const float* __restrict__ x2, const float* __restrict__ w,
                      const float* __restrict__ bias, float* __restrict__ out) {
    int gw = (blockIdx.x * blockDim.x + threadIdx.x) >> 5;
    int lane = threadIdx.x & 31;
    if (gw >= MM) return;
    const float* xr = x2 + (size_t)gw * H2;
    float acc[LL];
#pragma unroll
    for (int l = 0; l < LL; l++) acc[l] = 0.0f;
    for (int k = lane; k < H2; k += 32) {
        float xv = xr[k];
#pragma unroll
        for (int l = 0; l < LL; l++) acc[l] = fmaf(xv, w[l * H2 + k], acc[l]);
    }
#pragma unroll
    for (int l = 0; l < LL; l++) {
#pragma unroll
        for (int off = 16; off > 0; off >>= 1)
            acc[l] += __shfl_xor_sync(0xffffffffu, acc[l], off);
    }
    if (lane == 0) {
        int t = gw >> 5, b = gw & 31;
        float* o = out + 1 + ((size_t)b * TT + t) * LL;
#pragma unroll
        for (int l = 0; l < LL; l++) o[l] = acc[l] + bias[l];
    }
}

// ---------------- CRF NLL ----------------
__global__ void crf_k(const float* __restrict__ dout, const int* __restrict__ labels,
                      const int* __restrict__ mask, const float* __restrict__ start,
                      const float* __restrict__ endv, const float* __restrict__ trans,
                      float* __restrict__ out) {
    __shared__ float alpha[BB][LL];
    __shared__ float sc[BB];
    __shared__ float lz[BB];
    __shared__ int   prev[BB];
    __shared__ float tr[LL][LL];
    int tid = threadIdx.x;
    int b = tid / LL, l = tid % LL;
    if (tid < LL * LL) tr[tid / LL][tid % LL] = trans[tid];
    __syncthreads();
    const float* em = dout + 1;

    alpha[b][l] = start[l] + em[((size_t)b * TT) * LL + l];
    if (l == 0) {
        int tg = labels[b * TT]; if (tg < 0) tg = 0;
        sc[b] = start[tg] + em[((size_t)b * TT) * LL + tg];
        prev[b] = tg;
    }
    __syncthreads();

    for (int t = 1; t < TT; t++) {
        int on = mask[b * TT + t];
        float m = -1e30f;
#pragma unroll
        for (int p = 0; p < LL; p++) m = fmaxf(m, alpha[b][p] + tr[p][l]);
        float s = 0.0f;
#pragma unroll
        for (int p = 0; p < LL; p++) s += __expf(alpha[b][p] + tr[p][l] - m);
        float nxt = m + __logf(s) + em[((size_t)b * TT + t) * LL + l];
        __syncthreads();
        if (on) alpha[b][l] = nxt;
        if (l == 0) {
            int tg = labels[b * TT + t]; if (tg < 0) tg = 0;
            float mk = (float)mask[b * TT + t];
            sc[b] += (tr[prev[b]][tg] + em[((size_t)b * TT + t) * LL + tg]) * mk;
            if (on) prev[b] = tg;
        }
        __syncthreads();
    }
    if (l == 0) {
        sc[b] += endv[prev[b]];
        float m = -1e30f;
#pragma unroll
        for (int p = 0; p < LL; p++) m = fmaxf(m, alpha[b][p] + endv[p]);
        float s = 0.0f;
#pragma unroll
        for (int p = 0; p < LL; p++) s += __expf(alpha[b][p] + endv[p] - m);
        lz[b] = m + __logf(s);
    }
    __syncthreads();
    if (tid == 0) {
        float loss = 0.0f;
        for (int bb = 0; bb < BB; bb++) loss += sc[bb] - lz[bb];
        out[0] = -loss / (float)BB;
    }
}

// ---------------- host launch ----------------
extern "C" void kernel_launch(void* const* d_in, const int* in_sizes, int n_in,
                              void* d_out, int out_size) {
    const int*   ids    = (const int*)d_in[0];
    const int*   amask  = (const int*)d_in[1];
    const int*   labels = (const int*)d_in[2];
    const float* emb    = (const float*)d_in[3];
    const float* w_ih_l0_f = (const float*)d_in[4];
    const float* w_hh_l0_f = (const float*)d_in[5];
    const float* b_ih_l0_f = (const float*)d_in[6];
    const float* b_hh_l0_f = (const float*)d_in[7];
    const float* w_ih_l0_r = (const float*)d_in[8];
    const float* w_hh_l0_r = (const float*)d_in[9];
    const float* b_ih_l0_r = (const float*)d_in[10];
    const float* b_hh_l0_r = (const float*)d_in[11];
    const float* w_ih_l1_f = (const float*)d_in[12];
    const float* w_hh_l1_f = (const float*)d_in[13];
    const float* b_ih_l1_f = (const float*)d_in[14];
    const float* b_hh_l1_f = (const float*)d_in[15];
    const float* w_ih_l1_r = (const float*)d_in[16];
    const float* w_hh_l1_r = (const float*)d_in[17];
    const float* b_ih_l1_r = (const float*)d_in[18];
    const float* b_hh_l1_r = (const float*)d_in[19];
    const float* cls_w  = (const float*)d_in[20];
    const float* cls_b  = (const float*)d_in[21];
    const float* crf_s  = (const float*)d_in[22];
    const float* crf_e  = (const float*)d_in[23];
    const float* crf_t  = (const float*)d_in[24];
    float* out = (float*)d_out;

    float *x0, *x1, *x2, *pref, *prer, *wT;
    cudaGetSymbolAddress((void**)&x0,   g_x0);
    cudaGetSymbolAddress((void**)&x1,   g_x1);
    cudaGetSymbolAddress((void**)&x2,   g_x2);
    cudaGetSymbolAddress((void**)&pref, g_pre_f);
    cudaGetSymbolAddress((void**)&prer, g_pre_r);
    cudaGetSymbolAddress((void**)&wT,   g_wT);

    // 116KB dynamic smem: forces 1 block/SM (2x116 > 228KB) so the 128-block
    // grid spreads across SMs; actual use is ~102KB.
    const int rec_smem = 118784;
    cudaFuncSetAttribute(lstm_rec, cudaFuncAttributeMaxDynamicSharedMemorySize, rec_smem);

    embed_k<<<(MM * EE / 4 + 255) / 256, 256>>>(ids, emb, x0);
    transpose_whh<<<(4 * GG * HH + 255) / 256, 256>>>(w_hh_l0_f, w_hh_l0_r,
                                                      w_hh_l1_f, w_hh_l1_r, wT);
    dim3 gg(GG / 128, MM / 128, 2);
    gemm_nt_128<<<gg, 256>>>(x0, EE, w_ih_l0_f, w_ih_l0_r,
                             b_ih_l0_f, b_hh_l0_f, b_ih_l0_r, b_hh_l0_r, pref, prer);
    lstm_rec<<<128, 256, rec_smem>>>(pref, prer, wT, wT + HH * GG, x1);
    gemm_nt_128<<<gg, 256>>>(x1, H2, w_ih_l1_f, w_ih_l1_r,
                             b_ih_l1_f, b_hh_l1_f, b_ih_l1_r, b_hh_l1_r, pref, prer);
    lstm_rec<<<128, 256, rec_smem>>>(pref, prer, wT + 2 * HH * GG, wT + 3 * HH * GG, x2);
    cls_k<<<(MM * 32 + 255) / 256, 256>>>(x2, cls_w, cls_b, out);
    crf_k<<<1, BB * LL>>>(out, labels, amask, crf_s, crf_e, crf_t, out);
}

// round 6
// speedup vs baseline: 3.1231x; 1.4871x over previous
#include <cuda_runtime.h>
#include <math.h>

// ---------------- problem constants ----------------
#define TT   256
#define BB   32
#define HH   512
#define GG   2048      // 4*H
#define EE   256
#define H2   1024      // 2*H
#define LL   9
#define MM   (TT*BB)   // 8192

// ---------------- device scratch ----------------
__device__ float g_x0[MM * EE];
__device__ float g_x1[MM * H2];
__device__ float g_x2[MM * H2];
__device__ float g_pre_f[(size_t)MM * GG];
__device__ float g_pre_r[(size_t)MM * GG];
__device__ float g_wT[4 * HH * GG];          // [mat][k][r]
__device__ float g_hT[2][2][HH][BB];         // [buf][dir][k][b]
__device__ unsigned g_cnt;
__device__ volatile unsigned g_gen;

// ---------------- packed f32x2 helpers ----------------
typedef unsigned long long ull;
union F4U { float4 f; ull u[2]; };

__device__ __forceinline__ ull pk2(float lo, float hi) {
    ull r; asm("mov.b64 %0, {%1,%2};" : "=l"(r) : "f"(lo), "f"(hi)); return r;
}
__device__ __forceinline__ ull fma2(ull a, ull b, ull c) {
    ull d; asm("fma.rn.f32x2 %0, %1, %2, %3;" : "=l"(d) : "l"(a), "l"(b), "l"(c)); return d;
}
__device__ __forceinline__ void upk2(ull v, float& lo, float& hi) {
    asm("mov.b64 {%0,%1}, %2;" : "=f"(lo), "=f"(hi) : "l"(v));
}

__device__ __forceinline__ float sigf(float x) { return 1.0f / (1.0f + __expf(-x)); }
__device__ __forceinline__ float tanhfast(float x) {
    float e = __expf(2.0f * x);
    return (e - 1.0f) / (e + 1.0f);
}

// ---------------- embedding ----------------
__global__ void embed_k(const int* __restrict__ ids, const float* __restrict__ table,
                        float* __restrict__ x0) {
    int gid = blockIdx.x * blockDim.x + threadIdx.x;
    if (gid >= MM * EE / 4) return;
    int e4 = gid & 63;
    int m  = gid >> 6;
    int t  = m >> 5;
    int b  = m & 31;
    int id = ids[b * TT + t];
    reinterpret_cast<float4*>(x0)[gid] =
        reinterpret_cast<const float4*>(table)[(size_t)id * 64 + e4];
}

// ---------------- transpose w_hh ----------------
__global__ void transpose_whh(const float* __restrict__ a, const float* __restrict__ b,
                              const float* __restrict__ c, const float* __restrict__ d,
                              float* __restrict__ wT) {
    int idx = blockIdx.x * blockDim.x + threadIdx.x;
    if (idx >= 4 * GG * HH) return;
    int mat = idx >> 20;
    int rem = idx & 0xFFFFF;
    int r = rem >> 9, k = rem & 511;
    const float* src = (mat == 0) ? a : (mat == 1) ? b : (mat == 2) ? c : d;
    wT[(size_t)mat * (HH * GG) + (size_t)k * GG + r] = src[rem];
}

// ---------------- SGEMM (f32x2, double-buffered regs) ----------------
__global__ __launch_bounds__(256) void gemm_nt_128(
    const float* __restrict__ A, int K,
    const float* __restrict__ Wf, const float* __restrict__ Wr,
    const float* __restrict__ b1f, const float* __restrict__ b2f,
    const float* __restrict__ b1r, const float* __restrict__ b2r,
    float* __restrict__ Cf, float* __restrict__ Cr) {
    const int N = GG;
    const float* W;  const float* b1; const float* b2; float* C;
    if (blockIdx.z == 0) { W = Wf; b1 = b1f; b2 = b2f; C = Cf; }
    else                 { W = Wr; b1 = b1r; b2 = b2r; C = Cr; }

    __shared__ float As[8][132];
    __shared__ float Bs[8][132];
    int tid = threadIdx.x;
    int m0 = blockIdx.y * 128, n0 = blockIdx.x * 128;
    int lr = tid >> 1;
    int lc = (tid & 1) * 4;
    int tx = tid & 15, ty = tid >> 4;

    ull acc[8][4];
#pragma unroll
    for (int i = 0; i < 8; i++)
#pragma unroll
        for (int j = 0; j < 4; j++) acc[i][j] = 0ull;

    const float* Ap = &A[(size_t)(m0 + lr) * K + lc];
    const float* Wp = &W[(size_t)(n0 + lr) * K + lc];

    float4 av = *reinterpret_cast<const float4*>(Ap);
    float4 bv = *reinterpret_cast<const float4*>(Wp);

    for (int k0 = 0; k0 < K; k0 += 8) {
        As[lc + 0][lr] = av.x; As[lc + 1][lr] = av.y;
        As[lc + 2][lr] = av.z; As[lc + 3][lr] = av.w;
        Bs[lc + 0][lr] = bv.x; Bs[lc + 1][lr] = bv.y;
        Bs[lc + 2][lr] = bv.z; Bs[lc + 3][lr] = bv.w;
        __syncthreads();
        if (k0 + 8 < K) {
            av = *reinterpret_cast<const float4*>(Ap + k0 + 8);
            bv = *reinterpret_cast<const float4*>(Wp + k0 + 8);
        }
#pragma unroll
        for (int kk = 0; kk < 8; kk++) {
            F4U a0, a1, c0, c1;
            a0.f = *reinterpret_cast<const float4*>(&As[kk][ty * 8]);
            a1.f = *reinterpret_cast<const float4*>(&As[kk][ty * 8 + 4]);
            c0.f = *reinterpret_cast<const float4*>(&Bs[kk][tx * 8]);
            c1.f = *reinterpret_cast<const float4*>(&Bs[kk][tx * 8 + 4]);
            ull bp0 = c0.u[0], bp1 = c0.u[1], bp2 = c1.u[0], bp3 = c1.u[1];
            float as[8] = {a0.f.x, a0.f.y, a0.f.z, a0.f.w,
                           a1.f.x, a1.f.y, a1.f.z, a1.f.w};
#pragma unroll
            for (int i = 0; i < 8; i++) {
                ull ap = pk2(as[i], as[i]);
                acc[i][0] = fma2(ap, bp0, acc[i][0]);
                acc[i][1] = fma2(ap, bp1, acc[i][1]);
                acc[i][2] = fma2(ap, bp2, acc[i][2]);
                acc[i][3] = fma2(ap, bp3, acc[i][3]);
            }
        }
        __syncthreads();
    }
#pragma unroll
    for (int i = 0; i < 8; i++) {
        int m = m0 + ty * 8 + i;
        float r[8];
#pragma unroll
        for (int j = 0; j < 4; j++) upk2(acc[i][j], r[2 * j], r[2 * j + 1]);
#pragma unroll
        for (int j = 0; j < 8; j += 4) {
            int n = n0 + tx * 8 + j;
            float4 o;
            o.x = r[j + 0] + b1[n + 0] + b2[n + 0];
            o.y = r[j + 1] + b1[n + 1] + b2[n + 1];
            o.z = r[j + 2] + b1[n + 2] + b2[n + 2];
            o.w = r[j + 3] + b1[n + 3] + b2[n + 3];
            *reinterpret_cast<float4*>(&C[(size_t)m * N + n]) = o;
        }
    }
}

// ---------------- persistent bidirectional LSTM recurrence (v3) ----------------
// 128 blocks (64/dir), 512 threads (16 warps). Block covers 8 units (32 gate
// rows) x 32 batches. W tile resident in smem. Each warp owns a 32-k chunk,
// stages its private h chunk gmem->smem (no block sync), dots via LDS only.
// Barrier: CG-style (single fence by tid0); xout store overlapped with spin.
__global__ __launch_bounds__(512) void lstm_rec(
    const float* __restrict__ pre_f, const float* __restrict__ pre_r,
    const float* __restrict__ wT_f, const float* __restrict__ wT_r,
    float* __restrict__ xout) {
    extern __shared__ float sm[];
    float* sW = sm;                         // [512][32]   16384 f
    float* sH = sm + 512 * 32;              // [16][32][32] 16384 f (per-warp chunks)
    float* sP = sH + 512 * 32;              // [16][32][34] 17408 f
    float* sG = sP + 16 * 32 * 34;          // [32][33]     1056 f

    int blk = blockIdx.x;
    int dir = blk >> 6;
    int j0 = (blk & 63) * 8;
    const float* pre = dir ? pre_r : pre_f;
    const float* wT  = dir ? wT_r  : wT_f;

    int tid = threadIdx.x;
    int warp = tid >> 5, lane = tid & 31;
    int it = lane >> 2, jt = lane & 3;       // dot tile: 4 rows x 8 batches
    int rr = tid >> 4, b0 = (tid & 15) * 2;  // reduction: row rr, 2 batches
    int r_glob = (rr >> 3) * HH + j0 + (rr & 7);
    int ua = tid >> 5, ba = tid & 31;        // activation (tid<256): unit, batch

    // load W tile once: sW[k][g*8+u] = wT[k][g*512+j0+u]
    for (int i = tid; i < 512 * 32; i += 512) {
        int k = i >> 5, rl = i & 31;
        int g = rl >> 3, u = rl & 7;
        sW[k * 32 + rl] = wT[(size_t)k * GG + g * HH + j0 + u];
    }

    // zero h buffer 0
    if (tid < 256) g_hT[0][dir][j0 + ua][ba] = 0.0f;
    float creg = 0.0f;

    // initial full grid barrier (h init + visibility)
    __threadfence();
    __syncthreads();
    if (tid == 0) {
        unsigned gen = g_gen;
        if (atomicAdd(&g_cnt, 1u) == 127u) {
            atomicExch(&g_cnt, 0u);
            __threadfence();
            g_gen = gen + 1u;
        } else {
            while (g_gen == gen) { }
        }
        __threadfence();
    }
    __syncthreads();

    float* sHw = sH + warp * 1024;
    const float* sWw = sW + warp * 32 * 32 + it * 4;

    for (int s = 0; s < TT; s++) {
        int t = dir ? (TT - 1 - s) : s;
        int cur = s & 1, nxt = cur ^ 1;

        // ---- per-warp staging: copy this warp's 32-k chunk of h (4KB) ----
        {
            const float4* hg = reinterpret_cast<const float4*>(&g_hT[cur][dir][0][0])
                               + warp * 256;
            float4* hd = reinterpret_cast<float4*>(sHw);
#pragma unroll
            for (int i = 0; i < 8; i++) hd[lane + i * 32] = hg[lane + i * 32];
        }

        // prefetch pre for reduce phase (independent of staging)
        const float* pre_t = pre + (size_t)t * (BB * GG) + r_glob;
        float p0 = pre_t[(size_t)(b0 + 0) * GG];
        float p1 = pre_t[(size_t)(b0 + 1) * GG];

        __syncwarp();

        // ---- dot: 32 kk, 4r x 8b register tile, all LDS ----
        ull acc[4][4];
#pragma unroll
        for (int i = 0; i < 4; i++)
#pragma unroll
            for (int p = 0; p < 4; p++) acc[i][p] = 0ull;

#pragma unroll 8
        for (int kk = 0; kk < 32; kk++) {
            F4U w4, ha, hb;
            w4.f = *reinterpret_cast<const float4*>(sWw + kk * 32);
            ha.f = *reinterpret_cast<const float4*>(sHw + kk * 32 + jt * 8);
            hb.f = *reinterpret_cast<const float4*>(sHw + kk * 32 + jt * 8 + 4);
            ull h0 = ha.u[0], h1 = ha.u[1], h2 = hb.u[0], h3 = hb.u[1];
            ull w;
            w = pk2(w4.f.x, w4.f.x);
            acc[0][0] = fma2(w, h0, acc[0][0]); acc[0][1] = fma2(w, h1, acc[0][1]);
            acc[0][2] = fma2(w, h2, acc[0][2]); acc[0][3] = fma2(w, h3, acc[0][3]);
            w = pk2(w4.f.y, w4.f.y);
            acc[1][0] = fma2(w, h0, acc[1][0]); acc[1][1] = fma2(w, h1, acc[1][1]);
            acc[1][2] = fma2(w, h2, acc[1][2]); acc[1][3] = fma2(w, h3, acc[1][3]);
            w = pk2(w4.f.z, w4.f.z);
            acc[2][0] = fma2(w, h0, acc[2][0]); acc[2][1] = fma2(w, h1, acc[2][1]);
            acc[2][2] = fma2(w, h2, acc[2][2]); acc[2][3] = fma2(w, h3, acc[2][3]);
            w = pk2(w4.f.w, w4.f.w);
            acc[3][0] = fma2(w, h0, acc[3][0]); acc[3][1] = fma2(w, h1, acc[3][1]);
            acc[3][2] = fma2(w, h2, acc[3][2]); acc[3][3] = fma2(w, h3, acc[3][3]);
        }

        // write partials sP[warp][it*4+i][jt*8 + 2p]
#pragma unroll
        for (int i = 0; i < 4; i++) {
            float* row = sP + ((warp * 32) + it * 4 + i) * 34 + jt * 8;
#pragma unroll
            for (int p = 0; p < 4; p++) {
                float lo, hi; upk2(acc[i][p], lo, hi);
                row[2 * p] = lo; row[2 * p + 1] = hi;
            }
        }
        __syncthreads();

        // ---- reduce 16 chunks + pre -> gates ----
        {
            float s0 = p0, s1 = p1;
#pragma unroll
            for (int c = 0; c < 16; c++) {
                float2 x = *reinterpret_cast<const float2*>(
                    sP + ((c * 32) + rr) * 34 + b0);
                s0 += x.x; s1 += x.y;
            }
            float* g = sG + rr * 33 + b0;
            g[0] = s0; g[1] = s1;
        }
        __syncthreads();

        // ---- activation + h store (tid < 256) ----
        float h = 0.0f;
        if (tid < 256) {
            float gi = sG[(0 + ua) * 33 + ba];
            float gf = sG[(8 + ua) * 33 + ba];
            float gc = sG[(16 + ua) * 33 + ba];
            float go = sG[(24 + ua) * 33 + ba];
            creg = sigf(gf) * creg + sigf(gi) * tanhfast(gc);
            h = sigf(go) * tanhfast(creg);
            g_hT[nxt][dir][j0 + ua][ba] = h;
        }
        __syncthreads();

        // ---- grid barrier, xout store overlapped with spin ----
        unsigned gen = 0;
        if (tid == 0) {
            gen = g_gen;
            __threadfence();
            if (atomicAdd(&g_cnt, 1u) == 127u) {
                atomicExch(&g_cnt, 0u);
                __threadfence();
                g_gen = gen + 1u;
            }
        }
        if (tid < 256)
            xout[((size_t)t * BB + ba) * H2 + dir * HH + j0 + ua] = h;
        if (tid == 0) {
            while (g_gen == gen) { }
            __threadfence();
        }
        __syncthreads();
    }
}

// ---------------- classifier ----------------
__global__ void cls_k(const float* __restrict__ x2, const float* __restrict__ w,
                      const float* __restrict__ bias, float* __restrict__ out) {
    int gw = (blockIdx.x * blockDim.x + threadIdx.x) >> 5;
    int lane = threadIdx.x & 31;
    if (gw >= MM) return;
    const float* xr = x2 + (size_t)gw * H2;
    float acc[LL];
#pragma unroll
    for (int l = 0; l < LL; l++) acc[l] = 0.0f;
    for (int k = lane; k < H2; k += 32) {
        float xv = xr[k];
#pragma unroll
        for (int l = 0; l < LL; l++) acc[l] = fmaf(xv, w[l * H2 + k], acc[l]);
    }
#pragma unroll
    for (int l = 0; l < LL; l++) {
#pragma unroll
        for (int off = 16; off > 0; off >>= 1)
            acc[l] += __shfl_xor_sync(0xffffffffu, acc[l], off);
    }
    if (lane == 0) {
        int t = gw >> 5, b = gw & 31;
        float* o = out + 1 + ((size_t)b * TT + t) * LL;
#pragma unroll
        for (int l = 0; l < LL; l++) o[l] = acc[l] + bias[l];
    }
}

// ---------------- CRF NLL ----------------
__global__ void crf_k(const float* __restrict__ dout, const int* __restrict__ labels,
                      const int* __restrict__ mask, const float* __restrict__ start,
                      const float* __restrict__ endv, const float* __restrict__ trans,
                      float* __restrict__ out) {
    __shared__ float alpha[BB][LL];
    __shared__ float sc[BB];
    __shared__ float lz[BB];
    __shared__ int   prev[BB];
    __shared__ float tr[LL][LL];
    int tid = threadIdx.x;
    int b = tid / LL, l = tid % LL;
    if (tid < LL * LL) tr[tid / LL][tid % LL] = trans[tid];
    __syncthreads();
    const float* em = dout + 1;

    alpha[b][l] = start[l] + em[((size_t)b * TT) * LL + l];
    if (l == 0) {
        int tg = labels[b * TT]; if (tg < 0) tg = 0;
        sc[b] = start[tg] + em[((size_t)b * TT) * LL + tg];
        prev[b] = tg;
    }
    __syncthreads();

    for (int t = 1; t < TT; t++) {
        int on = mask[b * TT + t];
        float m = -1e30f;
#pragma unroll
        for (int p = 0; p < LL; p++) m = fmaxf(m, alpha[b][p] + tr[p][l]);
        float s = 0.0f;
#pragma unroll
        for (int p = 0; p < LL; p++) s += __expf(alpha[b][p] + tr[p][l] - m);
        float nxt = m + __logf(s) + em[((size_t)b * TT + t) * LL + l];
        __syncthreads();
        if (on) alpha[b][l] = nxt;
        if (l == 0) {
            int tg = labels[b * TT + t]; if (tg < 0) tg = 0;
            float mk = (float)mask[b * TT + t];
            sc[b] += (tr[prev[b]][tg] + em[((size_t)b * TT + t) * LL + tg]) * mk;
            if (on) prev[b] = tg;
        }
        __syncthreads();
    }
    if (l == 0) {
        sc[b] += endv[prev[b]];
        float m = -1e30f;
#pragma unroll
        for (int p = 0; p < LL; p++) m = fmaxf(m, alpha[b][p] + endv[p]);
        float s = 0.0f;
#pragma unroll
        for (int p = 0; p < LL; p++) s += __expf(alpha[b][p] + endv[p] - m);
        lz[b] = m + __logf(s);
    }
    __syncthreads();
    if (tid == 0) {
        float loss = 0.0f;
        for (int bb = 0; bb < BB; bb++) loss += sc[bb] - lz[bb];
        out[0] = -loss / (float)BB;
    }
}

// ---------------- host launch ----------------
extern "C" void kernel_launch(void* const* d_in, const int* in_sizes, int n_in,
                              void* d_out, int out_size) {
    const int*   ids    = (const int*)d_in[0];
    const int*   amask  = (const int*)d_in[1];
    const int*   labels = (const int*)d_in[2];
    const float* emb    = (const float*)d_in[3];
    const float* w_ih_l0_f = (const float*)d_in[4];
    const float* w_hh_l0_f = (const float*)d_in[5];
    const float* b_ih_l0_f = (const float*)d_in[6];
    const float* b_hh_l0_f = (const float*)d_in[7];
    const float* w_ih_l0_r = (const float*)d_in[8];
    const float* w_hh_l0_r = (const float*)d_in[9];
    const float* b_ih_l0_r = (const float*)d_in[10];
    const float* b_hh_l0_r = (const float*)d_in[11];
    const float* w_ih_l1_f = (const float*)d_in[12];
    const float* w_hh_l1_f = (const float*)d_in[13];
    const float* b_ih_l1_f = (const float*)d_in[14];
    const float* b_hh_l1_f = (const float*)d_in[15];
    const float* w_ih_l1_r = (const float*)d_in[16];
    const float* w_hh_l1_r = (const float*)d_in[17];
    const float* b_ih_l1_r = (const float*)d_in[18];
    const float* b_hh_l1_r = (const float*)d_in[19];
    const float* cls_w  = (const float*)d_in[20];
    const float* cls_b  = (const float*)d_in[21];
    const float* crf_s  = (const float*)d_in[22];
    const float* crf_e  = (const float*)d_in[23];
    const float* crf_t  = (const float*)d_in[24];
    float* out = (float*)d_out;

    float *x0, *x1, *x2, *pref, *prer, *wT;
    cudaGetSymbolAddress((void**)&x0,   g_x0);
    cudaGetSymbolAddress((void**)&x1,   g_x1);
    cudaGetSymbolAddress((void**)&x2,   g_x2);
    cudaGetSymbolAddress((void**)&pref, g_pre_f);
    cudaGetSymbolAddress((void**)&prer, g_pre_r);
    cudaGetSymbolAddress((void**)&wT,   g_wT);

    // smem: sW 64K + sH 64K + sP 68K + sG 4.125K = 204928 B -> 1 block/SM
    const int rec_smem = (512 * 32 + 512 * 32 + 16 * 32 * 34 + 32 * 33) * 4;
    cudaFuncSetAttribute(lstm_rec, cudaFuncAttributeMaxDynamicSharedMemorySize, rec_smem);

    embed_k<<<(MM * EE / 4 + 255) / 256, 256>>>(ids, emb, x0);
    transpose_whh<<<(4 * GG * HH + 255) / 256, 256>>>(w_hh_l0_f, w_hh_l0_r,
                                                      w_hh_l1_f, w_hh_l1_r, wT);
    dim3 gg(GG / 128, MM / 128, 2);
    gemm_nt_128<<<gg, 256>>>(x0, EE, w_ih_l0_f, w_ih_l0_r,
                             b_ih_l0_f, b_hh_l0_f, b_ih_l0_r, b_hh_l0_r, pref, prer);
    lstm_rec<<<128, 512, rec_smem>>>(pref, prer, wT, wT + HH * GG, x1);
    gemm_nt_128<<<gg, 256>>>(x1, H2, w_ih_l1_f, w_ih_l1_r,
                             b_ih_l1_f, b_hh_l1_f, b_ih_l1_r, b_hh_l1_r, pref, prer);
    lstm_rec<<<128, 512, rec_smem>>>(pref, prer, wT + 2 * HH * GG, wT + 3 * HH * GG, x2);
    cls_k<<<(MM * 32 + 255) / 256, 256>>>(x2, cls_w, cls_b, out);
    crf_k<<<1, BB * LL>>>(out, labels, amask, crf_s, crf_e, crf_t, out);
}

// round 7
// speedup vs baseline: 3.1822x; 1.0189x over previous
#include <cuda_runtime.h>
#include <math.h>

// ---------------- problem constants ----------------
#define TT   256
#define BB   32
#define HH   512
#define GG   2048      // 4*H
#define EE   256
#define H2   1024      // 2*H
#define LL   9
#define MM   (TT*BB)   // 8192

// ---------------- device scratch ----------------
__device__ float g_x0[MM * EE];
__device__ float g_x1[MM * H2];
__device__ float g_x2[MM * H2];
__device__ float g_pre_f[(size_t)MM * GG];
__device__ float g_pre_r[(size_t)MM * GG];
__device__ float g_wT[4 * HH * GG];          // [mat][k][r]
__device__ float g_hT[2][2][HH][BB];         // [buf][dir][k][b]
__device__ volatile unsigned g_arr[128];     // per-block arrival slots
__device__ volatile unsigned g_gen;          // release flag

// ---------------- packed f32x2 helpers ----------------
typedef unsigned long long ull;
union F4U { float4 f; ull u[2]; };

__device__ __forceinline__ ull pk2(float lo, float hi) {
    ull r; asm("mov.b64 %0, {%1,%2};" : "=l"(r) : "f"(lo), "f"(hi)); return r;
}
__device__ __forceinline__ ull fma2(ull a, ull b, ull c) {
    ull d; asm("fma.rn.f32x2 %0, %1, %2, %3;" : "=l"(d) : "l"(a), "l"(b), "l"(c)); return d;
}
__device__ __forceinline__ void upk2(ull v, float& lo, float& hi) {
    asm("mov.b64 {%0,%1}, %2;" : "=f"(lo), "=f"(hi) : "l"(v));
}

__device__ __forceinline__ float sigf(float x) { return 1.0f / (1.0f + __expf(-x)); }
__device__ __forceinline__ float tanhfast(float x) {
    float e = __expf(2.0f * x);
    return (e - 1.0f) / (e + 1.0f);
}

// ---------------- embedding ----------------
__global__ void embed_k(const int* __restrict__ ids, const float* __restrict__ table,
                        float* __restrict__ x0) {
    int gid = blockIdx.x * blockDim.x + threadIdx.x;
    if (gid >= MM * EE / 4) return;
    int e4 = gid & 63;
    int m  = gid >> 6;
    int t  = m >> 5;
    int b  = m & 31;
    int id = ids[b * TT + t];
    reinterpret_cast<float4*>(x0)[gid] =
        reinterpret_cast<const float4*>(table)[(size_t)id * 64 + e4];
}

// ---------------- transpose w_hh ----------------
__global__ void transpose_whh(const float* __restrict__ a, const float* __restrict__ b,
                              const float* __restrict__ c, const float* __restrict__ d,
                              float* __restrict__ wT) {
    int idx = blockIdx.x * blockDim.x + threadIdx.x;
    if (idx >= 4 * GG * HH) return;
    int mat = idx >> 20;
    int rem = idx & 0xFFFFF;
    int r = rem >> 9, k = rem & 511;
    const float* src = (mat == 0) ? a : (mat == 1) ? b : (mat == 2) ? c : d;
    wT[(size_t)mat * (HH * GG) + (size_t)k * GG + r] = src[rem];
}

// ---------------- SGEMM (f32x2, smem double-buffered, 1 sync/k-step) ----------
__global__ __launch_bounds__(256) void gemm_nt_128(
    const float* __restrict__ A, int K,
    const float* __restrict__ Wf, const float* __restrict__ Wr,
    const float* __restrict__ b1f, const float* __restrict__ b2f,
    const float* __restrict__ b1r, const float* __restrict__ b2r,
    float* __restrict__ Cf, float* __restrict__ Cr) {
    const int N = GG;
    const float* W;  const float* b1; const float* b2; float* C;
    if (blockIdx.z == 0) { W = Wf; b1 = b1f; b2 = b2f; C = Cf; }
    else                 { W = Wr; b1 = b1r; b2 = b2r; C = Cr; }

    __shared__ float As[2][8][132];
    __shared__ float Bs[2][8][132];
    int tid = threadIdx.x;
    int m0 = blockIdx.y * 128, n0 = blockIdx.x * 128;
    int lr = tid >> 1;
    int lc = (tid & 1) * 4;
    int tx = tid & 15, ty = tid >> 4;

    ull acc[8][4];
#pragma unroll
    for (int i = 0; i < 8; i++)
#pragma unroll
        for (int j = 0; j < 4; j++) acc[i][j] = 0ull;

    const float* Ap = &A[(size_t)(m0 + lr) * K + lc];
    const float* Wp = &W[(size_t)(n0 + lr) * K + lc];

    float4 av = *reinterpret_cast<const float4*>(Ap);
    float4 bv = *reinterpret_cast<const float4*>(Wp);
    As[0][lc + 0][lr] = av.x; As[0][lc + 1][lr] = av.y;
    As[0][lc + 2][lr] = av.z; As[0][lc + 3][lr] = av.w;
    Bs[0][lc + 0][lr] = bv.x; Bs[0][lc + 1][lr] = bv.y;
    Bs[0][lc + 2][lr] = bv.z; Bs[0][lc + 3][lr] = bv.w;
    __syncthreads();

    int buf = 0;
    for (int k0 = 0; k0 < K; k0 += 8) {
        bool more = (k0 + 8 < K);
        if (more) {
            av = *reinterpret_cast<const float4*>(Ap + k0 + 8);
            bv = *reinterpret_cast<const float4*>(Wp + k0 + 8);
        }
#pragma unroll
        for (int kk = 0; kk < 8; kk++) {
            F4U a0, a1, c0, c1;
            a0.f = *reinterpret_cast<const float4*>(&As[buf][kk][ty * 8]);
            a1.f = *reinterpret_cast<const float4*>(&As[buf][kk][ty * 8 + 4]);
            c0.f = *reinterpret_cast<const float4*>(&Bs[buf][kk][tx * 8]);
            c1.f = *reinterpret_cast<const float4*>(&Bs[buf][kk][tx * 8 + 4]);
            ull bp0 = c0.u[0], bp1 = c0.u[1], bp2 = c1.u[0], bp3 = c1.u[1];
            float as[8] = {a0.f.x, a0.f.y, a0.f.z, a0.f.w,
                           a1.f.x, a1.f.y, a1.f.z, a1.f.w};
#pragma unroll
            for (int i = 0; i < 8; i++) {
                ull ap = pk2(as[i], as[i]);
                acc[i][0] = fma2(ap, bp0, acc[i][0]);
                acc[i][1] = fma2(ap, bp1, acc[i][1]);
                acc[i][2] = fma2(ap, bp2, acc[i][2]);
                acc[i][3] = fma2(ap, bp3, acc[i][3]);
            }
        }
        if (more) {
            int nb = buf ^ 1;
            As[nb][lc + 0][lr] = av.x; As[nb][lc + 1][lr] = av.y;
            As[nb][lc + 2][lr] = av.z; As[nb][lc + 3][lr] = av.w;
            Bs[nb][lc + 0][lr] = bv.x; Bs[nb][lc + 1][lr] = bv.y;
            Bs[nb][lc + 2][lr] = bv.z; Bs[nb][lc + 3][lr] = bv.w;
            __syncthreads();
            buf = nb;
        }
    }
#pragma unroll
    for (int i = 0; i < 8; i++) {
        int m = m0 + ty * 8 + i;
        float r[8];
#pragma unroll
        for (int j = 0; j < 4; j++) upk2(acc[i][j], r[2 * j], r[2 * j + 1]);
#pragma unroll
        for (int j = 0; j < 8; j += 4) {
            int n = n0 + tx * 8 + j;
            float4 o;
            o.x = r[j + 0] + b1[n + 0] + b2[n + 0];
            o.y = r[j + 1] + b1[n + 1] + b2[n + 1];
            o.z = r[j + 2] + b1[n + 2] + b2[n + 2];
            o.w = r[j + 3] + b1[n + 3] + b2[n + 3];
            *reinterpret_cast<float4*>(&C[(size_t)m * N + n]) = o;
        }
    }
}

// ---------------- persistent bidirectional LSTM recurrence (v4) ----------------
// Same compute as v3; grid barrier replaced by flat 2-phase scheme:
//   non-zero blocks: tid0 stores to its own g_arr slot, polls g_gen.
//   block 0: threads 1..127 poll the 127 slots in parallel, tid0 releases g_gen.
// No same-address atomics anywhere on the step critical path.
__global__ __launch_bounds__(512) void lstm_rec(
    const float* __restrict__ pre_f, const float* __restrict__ pre_r,
    const float* __restrict__ wT_f, const float* __restrict__ wT_r,
    float* __restrict__ xout) {
    extern __shared__ float sm[];
    float* sW = sm;                         // [512][32]
    float* sH = sm + 512 * 32;              // [16][32][32]
    float* sP = sH + 512 * 32;              // [16][32][34]
    float* sG = sP + 16 * 32 * 34;          // [32][33]

    int blk = blockIdx.x;
    int dir = blk >> 6;
    int j0 = (blk & 63) * 8;
    const float* pre = dir ? pre_r : pre_f;
    const float* wT  = dir ? wT_r  : wT_f;

    int tid = threadIdx.x;
    int warp = tid >> 5, lane = tid & 31;
    int it = lane >> 2, jt = lane & 3;
    int rr = tid >> 4, b0 = (tid & 15) * 2;
    int r_glob = (rr >> 3) * HH + j0 + (rr & 7);
    int ua = tid >> 5, ba = tid & 31;

    unsigned gen0 = g_gen;   // stable: no release happens before all blocks read

    for (int i = tid; i < 512 * 32; i += 512) {
        int k = i >> 5, rl = i & 31;
        int g = rl >> 3, u = rl & 7;
        sW[k * 32 + rl] = wT[(size_t)k * GG + g * HH + j0 + u];
    }

    if (tid < 256) g_hT[0][dir][j0 + ua][ba] = 0.0f;
    float creg = 0.0f;

    // ---- initial barrier (target gen0+1) ----
    __threadfence();
    __syncthreads();
    if (blk == 0) {
        if (tid >= 1 && tid < 128) {
            unsigned tg = gen0 + 1u;
            while ((int)(g_arr[tid] - tg) < 0) { }
            __threadfence();
        }
        __syncthreads();
        if (tid == 0) { __threadfence(); g_gen = gen0 + 1u; }
    } else {
        if (tid == 0) {
            g_arr[blk] = gen0 + 1u;
            unsigned tg = gen0 + 1u;
            while ((int)(g_gen - tg) < 0) { }
            __threadfence();
        }
        __syncthreads();
    }

    float* sHw = sH + warp * 1024;
    const float* sWw = sW + warp * 32 * 32 + it * 4;

    for (int s = 0; s < TT; s++) {
        int t = dir ? (TT - 1 - s) : s;
        int cur = s & 1, nxt = cur ^ 1;

        // per-warp staging of this warp's 32-k h chunk
        {
            const float4* hg = reinterpret_cast<const float4*>(&g_hT[cur][dir][0][0])
                               + warp * 256;
            float4* hd = reinterpret_cast<float4*>(sHw);
#pragma unroll
            for (int i = 0; i < 8; i++) hd[lane + i * 32] = hg[lane + i * 32];
        }

        const float* pre_t = pre + (size_t)t * (BB * GG) + r_glob;
        float p0 = pre_t[(size_t)(b0 + 0) * GG];
        float p1 = pre_t[(size_t)(b0 + 1) * GG];

        __syncwarp();

        ull acc[4][4];
#pragma unroll
        for (int i = 0; i < 4; i++)
#pragma unroll
            for (int p = 0; p < 4; p++) acc[i][p] = 0ull;

#pragma unroll 8
        for (int kk = 0; kk < 32; kk++) {
            F4U w4, ha, hb;
            w4.f = *reinterpret_cast<const float4*>(sWw + kk * 32);
            ha.f = *reinterpret_cast<const float4*>(sHw + kk * 32 + jt * 8);
            hb.f = *reinterpret_cast<const float4*>(sHw + kk * 32 + jt * 8 + 4);
            ull h0 = ha.u[0], h1 = ha.u[1], h2 = hb.u[0], h3 = hb.u[1];
            ull w;
            w = pk2(w4.f.x, w4.f.x);
            acc[0][0] = fma2(w, h0, acc[0][0]); acc[0][1] = fma2(w, h1, acc[0][1]);
            acc[0][2] = fma2(w, h2, acc[0][2]); acc[0][3] = fma2(w, h3, acc[0][3]);
            w = pk2(w4.f.y, w4.f.y);
            acc[1][0] = fma2(w, h0, acc[1][0]); acc[1][1] = fma2(w, h1, acc[1][1]);
            acc[1][2] = fma2(w, h2, acc[1][2]); acc[1][3] = fma2(w, h3, acc[1][3]);
            w = pk2(w4.f.z, w4.f.z);
            acc[2][0] = fma2(w, h0, acc[2][0]); acc[2][1] = fma2(w, h1, acc[2][1]);
            acc[2][2] = fma2(w, h2, acc[2][2]); acc[2][3] = fma2(w, h3, acc[2][3]);
            w = pk2(w4.f.w, w4.f.w);
            acc[3][0] = fma2(w, h0, acc[3][0]); acc[3][1] = fma2(w, h1, acc[3][1]);
            acc[3][2] = fma2(w, h2, acc[3][2]); acc[3][3] = fma2(w, h3, acc[3][3]);
        }

#pragma unroll
        for (int i = 0; i < 4; i++) {
            float* row = sP + ((warp * 32) + it * 4 + i) * 34 + jt * 8;
#pragma unroll
            for (int p = 0; p < 4; p++) {
                float lo, hi; upk2(acc[i][p], lo, hi);
                row[2 * p] = lo; row[2 * p + 1] = hi;
            }
        }
        __syncthreads();

        {
            float s0 = p0, s1 = p1;
#pragma unroll
            for (int c = 0; c < 16; c++) {
                float2 x = *reinterpret_cast<const float2*>(
                    sP + ((c * 32) + rr) * 34 + b0);
                s0 += x.x; s1 += x.y;
            }
            float* g = sG + rr * 33 + b0;
            g[0] = s0; g[1] = s1;
        }
        __syncthreads();

        float h = 0.0f;
        if (tid < 256) {
            float gi = sG[(0 + ua) * 33 + ba];
            float gf = sG[(8 + ua) * 33 + ba];
            float gc = sG[(16 + ua) * 33 + ba];
            float go = sG[(24 + ua) * 33 + ba];
            creg = sigf(gf) * creg + sigf(gi) * tanhfast(gc);
            h = sigf(go) * tanhfast(creg);
            g_hT[nxt][dir][j0 + ua][ba] = h;
            __threadfence();
        }
        __syncthreads();

        // ---- flat grid barrier, xout store overlapped ----
        unsigned tg = gen0 + (unsigned)s + 2u;
        if (blk == 0) {
            if (tid < 256)
                xout[((size_t)t * BB + ba) * H2 + dir * HH + j0 + ua] = h;
            if (tid >= 1 && tid < 128) {
                while ((int)(g_arr[tid] - tg) < 0) { }
                __threadfence();
            }
            __syncthreads();
            if (tid == 0) { __threadfence(); g_gen = tg; }
        } else {
            if (tid == 0) g_arr[blk] = tg;
            if (tid < 256)
                xout[((size_t)t * BB + ba) * H2 + dir * HH + j0 + ua] = h;
            if (tid == 0) {
                while ((int)(g_gen - tg) < 0) { }
                __threadfence();
            }
            __syncthreads();
        }
    }
}

// ---------------- classifier ----------------
__global__ void cls_k(const float* __restrict__ x2, const float* __restrict__ w,
                      const float* __restrict__ bias, float* __restrict__ out) {
    int gw = (blockIdx.x * blockDim.x + threadIdx.x) >> 5;
    int lane = threadIdx.x & 31;
    if (gw >= MM) return;
    const float* xr = x2 + (size_t)gw * H2;
    float acc[LL];
#pragma unroll
    for (int l = 0; l < LL; l++) acc[l] = 0.0f;
    for (int k = lane; k < H2; k += 32) {
        float xv = xr[k];
#pragma unroll
        for (int l = 0; l < LL; l++) acc[l] = fmaf(xv, w[l * H2 + k], acc[l]);
    }
#pragma unroll
    for (int l = 0; l < LL; l++) {
#pragma unroll
        for (int off = 16; off > 0; off >>= 1)
            acc[l] += __shfl_xor_sync(0xffffffffu, acc[l], off);
    }
    if (lane == 0) {
        int t = gw >> 5, b = gw & 31;
        float* o = out + 1 + ((size_t)b * TT + t) * LL;
#pragma unroll
        for (int l = 0; l < LL; l++) o[l] = acc[l] + bias[l];
    }
}

// ---------------- CRF NLL ----------------
__global__ void crf_k(const float* __restrict__ dout, const int* __restrict__ labels,
                      const int* __restrict__ mask, const float* __restrict__ start,
                      const float* __restrict__ endv, const float* __restrict__ trans,
                      float* __restrict__ out) {
    __shared__ float alpha[BB][LL];
    __shared__ float sc[BB];
    __shared__ float lz[BB];
    __shared__ int   prev[BB];
    __shared__ float tr[LL][LL];
    int tid = threadIdx.x;
    int b = tid / LL, l = tid % LL;
    if (tid < LL * LL) tr[tid / LL][tid % LL] = trans[tid];
    __syncthreads();
    const float* em = dout + 1;

    alpha[b][l] = start[l] + em[((size_t)b * TT) * LL + l];
    if (l == 0) {
        int tg = labels[b * TT]; if (tg < 0) tg = 0;
        sc[b] = start[tg] + em[((size_t)b * TT) * LL + tg];
        prev[b] = tg;
    }
    __syncthreads();

    for (int t = 1; t < TT; t++) {
        int on = mask[b * TT + t];
        float m = -1e30f;
#pragma unroll
        for (int p = 0; p < LL; p++) m = fmaxf(m, alpha[b][p] + tr[p][l]);
        float s = 0.0f;
#pragma unroll
        for (int p = 0; p < LL; p++) s += __expf(alpha[b][p] + tr[p][l] - m);
        float nxt = m + __logf(s) + em[((size_t)b * TT + t) * LL + l];
        __syncthreads();
        if (on) alpha[b][l] = nxt;
        if (l == 0) {
            int tg = labels[b * TT + t]; if (tg < 0) tg = 0;
            float mk = (float)mask[b * TT + t];
            sc[b] += (tr[prev[b]][tg] + em[((size_t)b * TT + t) * LL + tg]) * mk;
            if (on) prev[b] = tg;
        }
        __syncthreads();
    }
    if (l == 0) {
        sc[b] += endv[prev[b]];
        float m = -1e30f;
#pragma unroll
        for (int p = 0; p < LL; p++) m = fmaxf(m, alpha[b][p] + endv[p]);
        float s = 0.0f;
#pragma unroll
        for (int p = 0; p < LL; p++) s += __expf(alpha[b][p] + endv[p] - m);
        lz[b] = m + __logf(s);
    }
    __syncthreads();
    if (tid == 0) {
        float loss = 0.0f;
        for (int bb = 0; bb < BB; bb++) loss += sc[bb] - lz[bb];
        out[0] = -loss / (float)BB;
    }
}

// ---------------- host launch ----------------
extern "C" void kernel_launch(void* const* d_in, const int* in_sizes, int n_in,
                              void* d_out, int out_size) {
    const int*   ids    = (const int*)d_in[0];
    const int*   amask  = (const int*)d_in[1];
    const int*   labels = (const int*)d_in[2];
    const float* emb    = (const float*)d_in[3];
    const float* w_ih_l0_f = (const float*)d_in[4];
    const float* w_hh_l0_f = (const float*)d_in[5];
    const float* b_ih_l0_f = (const float*)d_in[6];
    const float* b_hh_l0_f = (const float*)d_in[7];
    const float* w_ih_l0_r = (const float*)d_in[8];
    const float* w_hh_l0_r = (const float*)d_in[9];
    const float* b_ih_l0_r = (const float*)d_in[10];
    const float* b_hh_l0_r = (const float*)d_in[11];
    const float* w_ih_l1_f = (const float*)d_in[12];
    const float* w_hh_l1_f = (const float*)d_in[13];
    const float* b_ih_l1_f = (const float*)d_in[14];
    const float* b_hh_l1_f = (const float*)d_in[15];
    const float* w_ih_l1_r = (const float*)d_in[16];
    const float* w_hh_l1_r = (const float*)d_in[17];
    const float* b_ih_l1_r = (const float*)d_in[18];
    const float* b_hh_l1_r = (const float*)d_in[19];
    const float* cls_w  = (const float*)d_in[20];
    const float* cls_b  = (const float*)d_in[21];
    const float* crf_s  = (const float*)d_in[22];
    const float* crf_e  = (const float*)d_in[23];
    const float* crf_t  = (const float*)d_in[24];
    float* out = (float*)d_out;

    float *x0, *x1, *x2, *pref, *prer, *wT;
    cudaGetSymbolAddress((void**)&x0,   g_x0);
    cudaGetSymbolAddress((void**)&x1,   g_x1);
    cudaGetSymbolAddress((void**)&x2,   g_x2);
    cudaGetSymbolAddress((void**)&pref, g_pre_f);
    cudaGetSymbolAddress((void**)&prer, g_pre_r);
    cudaGetSymbolAddress((void**)&wT,   g_wT);

    const int rec_smem = (512 * 32 + 512 * 32 + 16 * 32 * 34 + 32 * 33) * 4;
    cudaFuncSetAttribute(lstm_rec, cudaFuncAttributeMaxDynamicSharedMemorySize, rec_smem);

    embed_k<<<(MM * EE / 4 + 255) / 256, 256>>>(ids, emb, x0);
    transpose_whh<<<(4 * GG * HH + 255) / 256, 256>>>(w_hh_l0_f, w_hh_l0_r,
                                                      w_hh_l1_f, w_hh_l1_r, wT);
    dim3 gg(GG / 128, MM / 128, 2);
    gemm_nt_128<<<gg, 256>>>(x0, EE, w_ih_l0_f, w_ih_l0_r,
                             b_ih_l0_f, b_hh_l0_f, b_ih_l0_r, b_hh_l0_r, pref, prer);
    lstm_rec<<<128, 512, rec_smem>>>(pref, prer, wT, wT + HH * GG, x1);
    gemm_nt_128<<<gg, 256>>>(x1, H2, w_ih_l1_f, w_ih_l1_r,
                             b_ih_l1_f, b_hh_l1_f, b_ih_l1_r, b_hh_l1_r, pref, prer);
    lstm_rec<<<128, 512, rec_smem>>>(pref, prer, wT + 2 * HH * GG, wT + 3 * HH * GG, x2);
    cls_k<<<(MM * 32 + 255) / 256, 256>>>(x2, cls_w, cls_b, out);
    crf_k<<<1, BB * LL>>>(out, labels, amask, crf_s, crf_e, crf_t, out);
}

// round 12
// speedup vs baseline: 3.8213x; 1.2008x over previous
#include <cuda_runtime.h>
#include <cuda_bf16.h>
#include <cstdint>
#include <math.h>

// ---------------- problem constants ----------------
#define TT   256
#define BB   32
#define HH   512
#define GG   2048      // 4*H
#define EE   256
#define H2   1024      // 2*H
#define LL   9
#define MM   (TT*BB)   // 8192

// ---------------- device scratch ----------------
__device__ float g_x0[MM * EE];
__device__ float g_x1[MM * H2];
__device__ float g_x2[MM * H2];
__device__ float g_pre_f[(size_t)MM * GG];
__device__ float g_pre_r[(size_t)MM * GG];
__device__ float g_wT[4 * HH * GG];          // [mat][k][r]
__device__ float g_hT[2][2][HH][BB];         // [buf][dir][k][b]
__device__ volatile unsigned g_arr[128];
__device__ volatile unsigned g_gen;
// bf16 split buffers
__device__ unsigned short g_Ah[MM * H2];     // A hi   (max K = 1024)
__device__ unsigned short g_Am[MM * H2];     // A mid
__device__ unsigned short g_Whf[GG * H2];    // W hi, fwd dir
__device__ unsigned short g_Wmf[GG * H2];
__device__ unsigned short g_Whr[GG * H2];    // W hi, rev dir
__device__ unsigned short g_Wmr[GG * H2];

// ---------------- packed f32x2 helpers ----------------
typedef unsigned long long ull;
union F4U { float4 f; ull u[2]; };

__device__ __forceinline__ ull pk2(float lo, float hi) {
    ull r; asm("mov.b64 %0, {%1,%2};" : "=l"(r) : "f"(lo), "f"(hi)); return r;
}
__device__ __forceinline__ ull fma2(ull a, ull b, ull c) {
    ull d; asm("fma.rn.f32x2 %0, %1, %2, %3;" : "=l"(d) : "l"(a), "l"(b), "l"(c)); return d;
}
__device__ __forceinline__ void upk2(ull v, float& lo, float& hi) {
    asm("mov.b64 {%0,%1}, %2;" : "=f"(lo), "=f"(hi) : "l"(v));
}

__device__ __forceinline__ float sigf(float x) { return 1.0f / (1.0f + __expf(-x)); }
__device__ __forceinline__ float tanhfast(float x) {
    float e = __expf(2.0f * x);
    return (e - 1.0f) / (e + 1.0f);
}

__device__ __forceinline__ unsigned smem_u32(const void* p) {
    unsigned a;
    asm("{ .reg .u64 t; cvta.to.shared.u64 t, %1; cvt.u32.u64 %0, t; }"
        : "=r"(a) : "l"(p));
    return a;
}

// ---------------- mma.sync helpers (classic HMMA path) ----------------
__device__ __forceinline__ void ldsm4(unsigned& r0, unsigned& r1, unsigned& r2,
                                      unsigned& r3, unsigned addr) {
    asm volatile("ldmatrix.sync.aligned.m8n8.x4.shared.b16 {%0,%1,%2,%3}, [%4];"
                 : "=r"(r0), "=r"(r1), "=r"(r2), "=r"(r3) : "r"(addr));
}
__device__ __forceinline__ void mma_bf16(float& d0, float& d1, float& d2, float& d3,
                                         unsigned a0, unsigned a1, unsigned a2,
                                         unsigned a3, unsigned b0, unsigned b1) {
    asm volatile(
        "mma.sync.aligned.m16n8k16.row.col.f32.bf16.bf16.f32 "
        "{%0,%1,%2,%3}, {%4,%5,%6,%7}, {%8,%9}, {%0,%1,%2,%3};"
        : "+f"(d0), "+f"(d1), "+f"(d2), "+f"(d3)
        : "r"(a0), "r"(a1), "r"(a2), "r"(a3), "r"(b0), "r"(b1));
}

// ---------------- embedding ----------------
__global__ void embed_k(const int* __restrict__ ids, const float* __restrict__ table,
                        float* __restrict__ x0) {
    int gid = blockIdx.x * blockDim.x + threadIdx.x;
    if (gid >= MM * EE / 4) return;
    int e4 = gid & 63;
    int m  = gid >> 6;
    int t  = m >> 5;
    int b  = m & 31;
    int id = ids[b * TT + t];
    reinterpret_cast<float4*>(x0)[gid] =
        reinterpret_cast<const float4*>(table)[(size_t)id * 64 + e4];
}

// ---------------- transpose w_hh ----------------
__global__ void transpose_whh(const float* __restrict__ a, const float* __restrict__ b,
                              const float* __restrict__ c, const float* __restrict__ d,
                              float* __restrict__ wT) {
    int idx = blockIdx.x * blockDim.x + threadIdx.x;
    if (idx >= 4 * GG * HH) return;
    int mat = idx >> 20;
    int rem = idx & 0xFFFFF;
    int r = rem >> 9, k = rem & 511;
    const float* src = (mat == 0) ? a : (mat == 1) ? b : (mat == 2) ? c : d;
    wT[(size_t)mat * (HH * GG) + (size_t)k * GG + r] = src[rem];
}

// ---------------- fp32 -> (bf16 hi, bf16 mid) split ----------------
__global__ void split_bf16(const float* __restrict__ src, unsigned short* __restrict__ hi,
                           unsigned short* __restrict__ mid, int n4) {
    int i = blockIdx.x * blockDim.x + threadIdx.x;
    if (i >= n4) return;
    float4 x = reinterpret_cast<const float4*>(src)[i];
    ushort4 h, m;
    __nv_bfloat16 t;
    t = __float2bfloat16(x.x); h.x = __bfloat16_as_ushort(t);
    m.x = __bfloat16_as_ushort(__float2bfloat16(x.x - __bfloat162float(t)));
    t = __float2bfloat16(x.y); h.y = __bfloat16_as_ushort(t);
    m.y = __bfloat16_as_ushort(__float2bfloat16(x.y - __bfloat162float(t)));
    t = __float2bfloat16(x.z); h.z = __bfloat16_as_ushort(t);
    m.z = __bfloat16_as_ushort(__float2bfloat16(x.z - __bfloat162float(t)));
    t = __float2bfloat16(x.w); h.w = __bfloat16_as_ushort(t);
    m.w = __bfloat16_as_ushort(__float2bfloat16(x.w - __bfloat162float(t)));
    reinterpret_cast<ushort4*>(hi)[i]  = h;
    reinterpret_cast<ushort4*>(mid)[i] = m;
}

// ---------------- mma.sync bf16 split GEMM ----------------
// C[m][n] = sum_k A[m][k]*W[n][k] + b1[n] + b2[n], via Ah*Bh + Ah*Bm + Am*Bh.
// Block 256 thr, tile 128x128, Kc=32. Warp tile 64x32 (4x4 of m16n8k16).
// smem rows padded to 80B -> ldmatrix conflict-free.
#define RSB 80
#define TLB (128 * RSB)        // 10240 bytes per operand tile
__global__ __launch_bounds__(256, 2) void gemm_mma(
    const unsigned short* __restrict__ Ah, const unsigned short* __restrict__ Am, int K,
    const float* __restrict__ b1f, const float* __restrict__ b2f,
    const float* __restrict__ b1r, const float* __restrict__ b2r,
    float* __restrict__ Cf, float* __restrict__ Cr) {
    __shared__ unsigned char sraw[4 * TLB];   // [Ah | Am | Bh | Bm]
    __shared__ float sbias[128];

    const unsigned short *Wh, *Wm; const float *b1, *b2; float* C;
    if (blockIdx.z == 0) { Wh = g_Whf; Wm = g_Wmf; b1 = b1f; b2 = b2f; C = Cf; }
    else                 { Wh = g_Whr; Wm = g_Wmr; b1 = b1r; b2 = b2r; C = Cr; }

    int m0 = blockIdx.y * 128, n0 = blockIdx.x * 128;
    int tid = threadIdx.x, warp = tid >> 5, lane = tid & 31;
    int wm = warp >> 2, wn = warp & 3;       // warp grid 2(m) x 4(n)

    if (tid < 128) sbias[tid] = b1[n0 + tid] + b2[n0 + tid];

    unsigned sbase = smem_u32(sraw);
    // ldmatrix lane addressing (x4 tiles: r0=lo8/klo, r1=hi8/klo, r2=lo8/khi, r3=hi8/khi)
    int tl = lane >> 3, r8 = lane & 7;
    int mn_off = (tl & 1) * 8 + r8;
    int k_off = (tl >> 1) * 8;

    float d[4][4][4];
#pragma unroll
    for (int i = 0; i < 4; i++)
#pragma unroll
        for (int j = 0; j < 4; j++)
#pragma unroll
            for (int q = 0; q < 4; q++) d[i][j][q] = 0.0f;

    int ldr = tid >> 1, ldh = tid & 1;       // gmem->smem: row, 32-byte half

    for (int kc0 = 0; kc0 < K; kc0 += 32) {
        // ---- load 4 operand tiles (128 rows x 32 bf16 = 8192 B each) ----
        // 2 threads per row; each stores its 32-byte half as TWO uint4s.
        {
            size_t ga = (size_t)(m0 + ldr) * K + kc0 + ldh * 16;
            size_t gb = (size_t)(n0 + ldr) * K + kc0 + ldh * 16;
            unsigned so = ldr * RSB + ldh * 32;
            *reinterpret_cast<uint4*>(sraw + 0 * TLB + so) =
                *reinterpret_cast<const uint4*>(Ah + ga);
            *reinterpret_cast<uint4*>(sraw + 0 * TLB + so + 16) =
                *reinterpret_cast<const uint4*>(Ah + ga + 8);
            *reinterpret_cast<uint4*>(sraw + 1 * TLB + so) =
                *reinterpret_cast<const uint4*>(Am + ga);
            *reinterpret_cast<uint4*>(sraw + 1 * TLB + so + 16) =
                *reinterpret_cast<const uint4*>(Am + ga + 8);
            *reinterpret_cast<uint4*>(sraw + 2 * TLB + so) =
                *reinterpret_cast<const uint4*>(Wh + gb);
            *reinterpret_cast<uint4*>(sraw + 2 * TLB + so + 16) =
                *reinterpret_cast<const uint4*>(Wh + gb + 8);
            *reinterpret_cast<uint4*>(sraw + 3 * TLB + so) =
                *reinterpret_cast<const uint4*>(Wm + gb);
            *reinterpret_cast<uint4*>(sraw + 3 * TLB + so + 16) =
                *reinterpret_cast<const uint4*>(Wm + gb + 8);
        }
        __syncthreads();

#pragma unroll
        for (int kh = 0; kh < 2; kh++) {
            // 3 passes: (Ah,Bh), (Ah,Bm), (Am,Bh)
#pragma unroll
            for (int ps = 0; ps < 3; ps++) {
                unsigned ab = (ps == 2) ? 1u * TLB : 0u * TLB;
                unsigned bb = (ps == 1) ? 3u * TLB : 2u * TLB;
                unsigned a[4][4], bfr[2][4];
#pragma unroll
                for (int i = 0; i < 4; i++) {
                    unsigned ao = sbase + ab +
                        (wm * 64 + i * 16 + mn_off) * RSB + (kh * 16 + k_off) * 2;
                    ldsm4(a[i][0], a[i][1], a[i][2], a[i][3], ao);
                }
#pragma unroll
                for (int j16 = 0; j16 < 2; j16++) {
                    unsigned bo = sbase + bb +
                        (wn * 32 + j16 * 16 + mn_off) * RSB + (kh * 16 + k_off) * 2;
                    ldsm4(bfr[j16][0], bfr[j16][1], bfr[j16][2], bfr[j16][3], bo);
                }
#pragma unroll
                for (int i = 0; i < 4; i++)
#pragma unroll
                    for (int j = 0; j < 4; j++) {
                        int jj = j >> 1, p = j & 1;
                        mma_bf16(d[i][j][0], d[i][j][1], d[i][j][2], d[i][j][3],
                                 a[i][0], a[i][1], a[i][2], a[i][3],
                                 bfr[jj][p], bfr[jj][p + 2]);
                    }
            }
        }
        __syncthreads();
    }

    // ---- epilogue: d regs -> C with bias ----
    int r = lane >> 2, c2 = (lane & 3) * 2;
#pragma unroll
    for (int i = 0; i < 4; i++) {
#pragma unroll
        for (int j = 0; j < 4; j++) {
            int colL = wn * 32 + j * 8 + c2;
            int col = n0 + colL;
            int row0 = m0 + wm * 64 + i * 16 + r;
            float2 o0, o1;
            o0.x = d[i][j][0] + sbias[colL];
            o0.y = d[i][j][1] + sbias[colL + 1];
            o1.x = d[i][j][2] + sbias[colL];
            o1.y = d[i][j][3] + sbias[colL + 1];
            *reinterpret_cast<float2*>(C + (size_t)row0 * GG + col) = o0;
            *reinterpret_cast<float2*>(C + (size_t)(row0 + 8) * GG + col) = o1;
        }
    }
}

// ---------------- persistent bidirectional LSTM recurrence (v4, unchanged) -----
__global__ __launch_bounds__(512) void lstm_rec(
    const float* __restrict__ pre_f, const float* __restrict__ pre_r,
    const float* __restrict__ wT_f, const float* __restrict__ wT_r,
    float* __restrict__ xout) {
    extern __shared__ float smf[];
    float* sW = smf;
    float* sH = smf + 512 * 32;
    float* sP = sH + 512 * 32;
    float* sG = sP + 16 * 32 * 34;

    int blk = blockIdx.x;
    int dir = blk >> 6;
    int j0 = (blk & 63) * 8;
    const float* pre = dir ? pre_r : pre_f;
    const float* wT  = dir ? wT_r  : wT_f;

    int tid = threadIdx.x;
    int warp = tid >> 5, lane = tid & 31;
    int it = lane >> 2, jt = lane & 3;
    int rr = tid >> 4, b0 = (tid & 15) * 2;
    int r_glob = (rr >> 3) * HH + j0 + (rr & 7);
    int ua = tid >> 5, ba = tid & 31;

    unsigned gen0 = g_gen;

    for (int i = tid; i < 512 * 32; i += 512) {
        int k = i >> 5, rl = i & 31;
        int g = rl >> 3, u = rl & 7;
        sW[k * 32 + rl] = wT[(size_t)k * GG + g * HH + j0 + u];
    }

    if (tid < 256) g_hT[0][dir][j0 + ua][ba] = 0.0f;
    float creg = 0.0f;

    __threadfence();
    __syncthreads();
    if (blk == 0) {
        if (tid >= 1 && tid < 128) {
            unsigned tg = gen0 + 1u;
            while ((int)(g_arr[tid] - tg) < 0) { }
            __threadfence();
        }
        __syncthreads();
        if (tid == 0) { __threadfence(); g_gen = gen0 + 1u; }
    } else {
        if (tid == 0) {
            g_arr[blk] = gen0 + 1u;
            unsigned tg = gen0 + 1u;
            while ((int)(g_gen - tg) < 0) { }
            __threadfence();
        }
        __syncthreads();
    }

    float* sHw = sH + warp * 1024;
    const float* sWw = sW + warp * 32 * 32 + it * 4;

    for (int s = 0; s < TT; s++) {
        int t = dir ? (TT - 1 - s) : s;
        int cur = s & 1, nxt = cur ^ 1;

        {
            const float4* hg = reinterpret_cast<const float4*>(&g_hT[cur][dir][0][0])
                               + warp * 256;
            float4* hd = reinterpret_cast<float4*>(sHw);
#pragma unroll
            for (int i = 0; i < 8; i++) hd[lane + i * 32] = hg[lane + i * 32];
        }

        const float* pre_t = pre + (size_t)t * (BB * GG) + r_glob;
        float p0 = pre_t[(size_t)(b0 + 0) * GG];
        float p1 = pre_t[(size_t)(b0 + 1) * GG];

        __syncwarp();

        ull acc[4][4];
#pragma unroll
        for (int i = 0; i < 4; i++)
#pragma unroll
            for (int p = 0; p < 4; p++) acc[i][p] = 0ull;

#pragma unroll 8
        for (int kk = 0; kk < 32; kk++) {
            F4U w4, ha, hb;
            w4.f = *reinterpret_cast<const float4*>(sWw + kk * 32);
            ha.f = *reinterpret_cast<const float4*>(sHw + kk * 32 + jt * 8);
            hb.f = *reinterpret_cast<const float4*>(sHw + kk * 32 + jt * 8 + 4);
            ull h0 = ha.u[0], h1 = ha.u[1], h2 = hb.u[0], h3 = hb.u[1];
            ull w;
            w = pk2(w4.f.x, w4.f.x);
            acc[0][0] = fma2(w, h0, acc[0][0]); acc[0][1] = fma2(w, h1, acc[0][1]);
            acc[0][2] = fma2(w, h2, acc[0][2]); acc[0][3] = fma2(w, h3, acc[0][3]);
            w = pk2(w4.f.y, w4.f.y);
            acc[1][0] = fma2(w, h0, acc[1][0]); acc[1][1] = fma2(w, h1, acc[1][1]);
            acc[1][2] = fma2(w, h2, acc[1][2]); acc[1][3] = fma2(w, h3, acc[1][3]);
            w = pk2(w4.f.z, w4.f.z);
            acc[2][0] = fma2(w, h0, acc[2][0]); acc[2][1] = fma2(w, h1, acc[2][1]);
            acc[2][2] = fma2(w, h2, acc[2][2]); acc[2][3] = fma2(w, h3, acc[2][3]);
            w = pk2(w4.f.w, w4.f.w);
            acc[3][0] = fma2(w, h0, acc[3][0]); acc[3][1] = fma2(w, h1, acc[3][1]);
            acc[3][2] = fma2(w, h2, acc[3][2]); acc[3][3] = fma2(w, h3, acc[3][3]);
        }

#pragma unroll
        for (int i = 0; i < 4; i++) {
            float* row = sP + ((warp * 32) + it * 4 + i) * 34 + jt * 8;
#pragma unroll
            for (int p = 0; p < 4; p++) {
                float lo, hi; upk2(acc[i][p], lo, hi);
                row[2 * p] = lo; row[2 * p + 1] = hi;
            }
        }
        __syncthreads();

        {
            float s0 = p0, s1 = p1;
#pragma unroll
            for (int c = 0; c < 16; c++) {
                float2 x = *reinterpret_cast<const float2*>(
                    sP + ((c * 32) + rr) * 34 + b0);
                s0 += x.x; s1 += x.y;
            }
            float* g = sG + rr * 33 + b0;
            g[0] = s0; g[1] = s1;
        }
        __syncthreads();

        float h = 0.0f;
        if (tid < 256) {
            float gi = sG[(0 + ua) * 33 + ba];
            float gf = sG[(8 + ua) * 33 + ba];
            float gc = sG[(16 + ua) * 33 + ba];
            float go = sG[(24 + ua) * 33 + ba];
            creg = sigf(gf) * creg + sigf(gi) * tanhfast(gc);
            h = sigf(go) * tanhfast(creg);
            g_hT[nxt][dir][j0 + ua][ba] = h;
            __threadfence();
        }
        __syncthreads();

        unsigned tg = gen0 + (unsigned)s + 2u;
        if (blk == 0) {
            if (tid < 256)
                xout[((size_t)t * BB + ba) * H2 + dir * HH + j0 + ua] = h;
            if (tid >= 1 && tid < 128) {
                while ((int)(g_arr[tid] - tg) < 0) { }
                __threadfence();
            }
            __syncthreads();
            if (tid == 0) { __threadfence(); g_gen = tg; }
        } else {
            if (tid == 0) g_arr[blk] = tg;
            if (tid < 256)
                xout[((size_t)t * BB + ba) * H2 + dir * HH + j0 + ua] = h;
            if (tid == 0) {
                while ((int)(g_gen - tg) < 0) { }
                __threadfence();
            }
            __syncthreads();
        }
    }
}

// ---------------- classifier ----------------
__global__ void cls_k(const float* __restrict__ x2, const float* __restrict__ w,
                      const float* __restrict__ bias, float* __restrict__ out) {
    int gw = (blockIdx.x * blockDim.x + threadIdx.x) >> 5;
    int lane = threadIdx.x & 31;
    if (gw >= MM) return;
    const float* xr = x2 + (size_t)gw * H2;
    float acc[LL];
#pragma unroll
    for (int l = 0; l < LL; l++) acc[l] = 0.0f;
    for (int k = lane; k < H2; k += 32) {
        float xv = xr[k];
#pragma unroll
        for (int l = 0; l < LL; l++) acc[l] = fmaf(xv, w[l * H2 + k], acc[l]);
    }
#pragma unroll
    for (int l = 0; l < LL; l++) {
#pragma unroll
        for (int off = 16; off > 0; off >>= 1)
            acc[l] += __shfl_xor_sync(0xffffffffu, acc[l], off);
    }
    if (lane == 0) {
        int t = gw >> 5, b = gw & 31;
        float* o = out + 1 + ((size_t)b * TT + t) * LL;
#pragma unroll
        for (int l = 0; l < LL; l++) o[l] = acc[l] + bias[l];
    }
}

// ---------------- CRF NLL ----------------
__global__ void crf_k(const float* __restrict__ dout, const int* __restrict__ labels,
                      const int* __restrict__ mask, const float* __restrict__ start,
                      const float* __restrict__ endv, const float* __restrict__ trans,
                      float* __restrict__ out) {
    __shared__ float alpha[BB][LL];
    __shared__ float sc[BB];
    __shared__ float lz[BB];
    __shared__ int   prev[BB];
    __shared__ float tr[LL][LL];
    int tid = threadIdx.x;
    int b = tid / LL, l = tid % LL;
    if (tid < LL * LL) tr[tid / LL][tid % LL] = trans[tid];
    __syncthreads();
    const float* em = dout + 1;

    alpha[b][l] = start[l] + em[((size_t)b * TT) * LL + l];
    if (l == 0) {
        int tg = labels[b * TT]; if (tg < 0) tg = 0;
        sc[b] = start[tg] + em[((size_t)b * TT) * LL + tg];
        prev[b] = tg;
    }
    __syncthreads();

    for (int t = 1; t < TT; t++) {
        int on = mask[b * TT + t];
        float m = -1e30f;
#pragma unroll
        for (int p = 0; p < LL; p++) m = fmaxf(m, alpha[b][p] + tr[p][l]);
        float s = 0.0f;
#pragma unroll
        for (int p = 0; p < LL; p++) s += __expf(alpha[b][p] + tr[p][l] - m);
        float nxt = m + __logf(s) + em[((size_t)b * TT + t) * LL + l];
        __syncthreads();
        if (on) alpha[b][l] = nxt;
        if (l == 0) {
            int tg = labels[b * TT + t]; if (tg < 0) tg = 0;
            float mk = (float)mask[b * TT + t];
            sc[b] += (tr[prev[b]][tg] + em[((size_t)b * TT + t) * LL + tg]) * mk;
            if (on) prev[b] = tg;
        }
        __syncthreads();
    }
    if (l == 0) {
        sc[b] += endv[prev[b]];
        float m = -1e30f;
#pragma unroll
        for (int p = 0; p < LL; p++) m = fmaxf(m, alpha[b][p] + endv[p]);
        float s = 0.0f;
#pragma unroll
        for (int p = 0; p < LL; p++) s += __expf(alpha[b][p] + endv[p] - m);
        lz[b] = m + __logf(s);
    }
    __syncthreads();
    if (tid == 0) {
        float loss = 0.0f;
        for (int bb = 0; bb < BB; bb++) loss += sc[bb] - lz[bb];
        out[0] = -loss / (float)BB;
    }
}

// ---------------- host launch ----------------
extern "C" void kernel_launch(void* const* d_in, const int* in_sizes, int n_in,
                              void* d_out, int out_size) {
    const int*   ids    = (const int*)d_in[0];
    const int*   amask  = (const int*)d_in[1];
    const int*   labels = (const int*)d_in[2];
    const float* emb    = (const float*)d_in[3];
    const float* w_ih_l0_f = (const float*)d_in[4];
    const float* w_hh_l0_f = (const float*)d_in[5];
    const float* b_ih_l0_f = (const float*)d_in[6];
    const float* b_hh_l0_f = (const float*)d_in[7];
    const float* w_ih_l0_r = (const float*)d_in[8];
    const float* w_hh_l0_r = (const float*)d_in[9];
    const float* b_ih_l0_r = (const float*)d_in[10];
    const float* b_hh_l0_r = (const float*)d_in[11];
    const float* w_ih_l1_f = (const float*)d_in[12];
    const float* w_hh_l1_f = (const float*)d_in[13];
    const float* b_ih_l1_f = (const float*)d_in[14];
    const float* b_hh_l1_f = (const float*)d_in[15];
    const float* w_ih_l1_r = (const float*)d_in[16];
    const float* w_hh_l1_r = (const float*)d_in[17];
    const float* b_ih_l1_r = (const float*)d_in[18];
    const float* b_hh_l1_r = (const float*)d_in[19];
    const float* cls_w  = (const float*)d_in[20];
    const float* cls_b  = (const float*)d_in[21];
    const float* crf_s  = (const float*)d_in[22];
    const float* crf_e  = (const float*)d_in[23];
    const float* crf_t  = (const float*)d_in[24];
    float* out = (float*)d_out;

    float *x0, *x1, *x2, *pref, *prer, *wT;
    unsigned short *ah, *am, *whf, *wmf, *whr, *wmr;
    cudaGetSymbolAddress((void**)&x0,   g_x0);
    cudaGetSymbolAddress((void**)&x1,   g_x1);
    cudaGetSymbolAddress((void**)&x2,   g_x2);
    cudaGetSymbolAddress((void**)&pref, g_pre_f);
    cudaGetSymbolAddress((void**)&prer, g_pre_r);
    cudaGetSymbolAddress((void**)&wT,   g_wT);
    cudaGetSymbolAddress((void**)&ah,   g_Ah);
    cudaGetSymbolAddress((void**)&am,   g_Am);
    cudaGetSymbolAddress((void**)&whf,  g_Whf);
    cudaGetSymbolAddress((void**)&wmf,  g_Wmf);
    cudaGetSymbolAddress((void**)&whr,  g_Whr);
    cudaGetSymbolAddress((void**)&wmr,  g_Wmr);

    const int rec_smem = (512 * 32 + 512 * 32 + 16 * 32 * 34 + 32 * 33) * 4;
    cudaFuncSetAttribute(lstm_rec, cudaFuncAttributeMaxDynamicSharedMemorySize, rec_smem);

    embed_k<<<(MM * EE / 4 + 255) / 256, 256>>>(ids, emb, x0);
    transpose_whh<<<(4 * GG * HH + 255) / 256, 256>>>(w_hh_l0_f, w_hh_l0_r,
                                                      w_hh_l1_f, w_hh_l1_r, wT);

    // ---- layer 0 ----
    split_bf16<<<(MM * EE / 4 + 255) / 256, 256>>>(x0, ah, am, MM * EE / 4);
    split_bf16<<<(GG * EE / 4 + 255) / 256, 256>>>(w_ih_l0_f, whf, wmf, GG * EE / 4);
    split_bf16<<<(GG * EE / 4 + 255) / 256, 256>>>(w_ih_l0_r, whr, wmr, GG * EE / 4);
    {
        dim3 gg(GG / 128, MM / 128, 2);
        gemm_mma<<<gg, 256>>>(ah, am, EE,
                              b_ih_l0_f, b_hh_l0_f, b_ih_l0_r, b_hh_l0_r,
                              pref, prer);
    }
    lstm_rec<<<128, 512, rec_smem>>>(pref, prer, wT, wT + HH * GG, x1);

    // ---- layer 1 ----
    split_bf16<<<(MM * H2 / 4 + 255) / 256, 256>>>(x1, ah, am, MM * H2 / 4);
    split_bf16<<<(GG * H2 / 4 + 255) / 256, 256>>>(w_ih_l1_f, whf, wmf, GG * H2 / 4);
    split_bf16<<<(GG * H2 / 4 + 255) / 256, 256>>>(w_ih_l1_r, whr, wmr, GG * H2 / 4);
    {
        dim3 gg(GG / 128, MM / 128, 2);
        gemm_mma<<<gg, 256>>>(ah, am, H2,
                              b_ih_l1_f, b_hh_l1_f, b_ih_l1_r, b_hh_l1_r,
                              pref, prer);
    }
    lstm_rec<<<128, 512, rec_smem>>>(pref, prer, wT + 2 * HH * GG, wT + 3 * HH * GG, x2);

    cls_k<<<(MM * 32 + 255) / 256, 256>>>(x2, cls_w, cls_b, out);
    crf_k<<<1, BB * LL>>>(out, labels, amask, crf_s, crf_e, crf_t, out);
}